// round 5
// baseline (speedup 1.0000x reference)
#include <cuda_runtime.h>
#include <cstdint>

// ---------------- problem constants ----------------
#define NB     2048
#define F0V    39
#define DDIM   16
#define P0     1521
#define P1     4992

// chunk schedule: 6 passes x 39 f-chunks
//  pass 0: layer1, q-window [0,32),  Kc=32
//  pass 1: layer1, q-window [32,40), Kc=8  (q=39 zero-padded)
//  pass 2-5: layer2, q-window [32w,32w+32), Kc=32
#define NPASS  6
#define NF     39
#define NCHUNK (NPASS * NF)      // 234
#define CS_BIG 4096              // floats per Kc=32 W chunk (128n x 32k)
#define CS_SM  1024              // floats per Kc=8 chunk
#define WP_TOTAL (NF * CS_BIG * 5 + NF * CS_SM)   // 838656 floats

#define NTHR   512
#define NSTG   4                 // cp.async pipeline stages

// ---------------- smem layout (bytes) ----------------
#define OFF_X    0               // 128 x 40 fp32 = 20480
#define OFF_H1   20480           // 128 x 132 fp32 = 67584
#define OFF_B    88064           // NSTG x 16384 W buffers
#define SMEM_TOTAL (OFF_B + NSTG * 16384)   // 153600

__device__ float g_Wp[WP_TOTAL];

// ---------------- helpers ----------------
__device__ __forceinline__ uint32_t smem_u32(const void* p) {
    uint32_t a;
    asm("{ .reg .u64 t; cvta.to.shared.u64 t, %1; cvt.u32.u64 %0, t; }" : "=r"(a) : "l"(p));
    return a;
}
__device__ __forceinline__ uint32_t f2tf(float x) {
    uint32_t r;
    asm("cvt.rna.tf32.f32 %0, %1;" : "=r"(r) : "f"(x));
    return r;
}
__device__ __forceinline__ void mma_tf32(float* c, const uint32_t* a, uint32_t b0, uint32_t b1) {
    asm volatile(
        "mma.sync.aligned.m16n8k8.row.col.f32.tf32.tf32.f32 "
        "{%0,%1,%2,%3},{%4,%5,%6,%7},{%8,%9},{%0,%1,%2,%3};"
        : "+f"(c[0]), "+f"(c[1]), "+f"(c[2]), "+f"(c[3])
        : "r"(a[0]), "r"(a[1]), "r"(a[2]), "r"(a[3]), "r"(b0), "r"(b1));
}

__device__ __forceinline__ int pass_base(int p) {
    if (p == 0) return 0;
    if (p == 1) return NF * CS_BIG;
    return NF * CS_BIG + NF * CS_SM + (p - 2) * NF * CS_BIG;
}

// ---------------- prepass: W -> tf32 fragment-packed layout ----------------
// Kc=32 chunk layout: float4[nbg(16)][ks2(2)][lane(32)]:
//   .x=b0(ks=2ks2) .y=b1(ks=2ks2) .z=b0(ks=2ks2+1) .w=b1(ks=2ks2+1)
//   b0: k = 8*ks + lane%4 ; b1: k = 8*ks + lane%4 + 4 ; n = nbg*8 + lane/4
// Kc=8 chunk layout: float2[nbg(16)][lane(32)] = {b0, b1}
__global__ void prep_kernel(const float* __restrict__ W0, const float* __restrict__ W1) {
    for (int idx = blockIdx.x * blockDim.x + threadIdx.x; idx < WP_TOTAL;
         idx += gridDim.x * blockDim.x) {
        int p, rem;
        if (idx < NF * CS_BIG) { p = 0; rem = idx; }
        else if (idx < NF * CS_BIG + NF * CS_SM) { p = 1; rem = idx - NF * CS_BIG; }
        else {
            int j = idx - (NF * CS_BIG + NF * CS_SM);
            p = 2 + j / (NF * CS_BIG);
            rem = j % (NF * CS_BIG);
        }
        int cs = (p == 1) ? CS_SM : CS_BIG;
        int f = rem / cs, r = rem - f * cs;
        int n, kl;
        if (p == 1) {
            int q2 = r >> 1, comp = r & 1;
            int lane = q2 & 31, nbg = q2 >> 5;
            kl = comp * 4 + (lane & 3);
            n = nbg * 8 + (lane >> 2);
        } else {
            int q4 = r >> 2, comp = r & 3;
            int lane = q4 & 31, ks2 = (q4 >> 5) & 1, nbg = q4 >> 6;
            kl = ks2 * 16 + comp * 4 + (lane & 3);
            n = nbg * 8 + (lane >> 2);
        }
        float v;
        if (p == 0) {
            v = W0[n * P0 + f * F0V + kl];                 // q = kl < 32 < 39
        } else if (p == 1) {
            int q = 32 + kl;
            v = (q < F0V) ? W0[n * P0 + f * F0V + q] : 0.0f;
        } else {
            int q = 32 * (p - 2) + kl;
            v = W1[n * P1 + f * 128 + q];
        }
        g_Wp[idx] = __uint_as_float(f2tf(v));
    }
}

// ---------------- cp.async W prefetch (512 threads) ----------------
__device__ __forceinline__ void prefetch_chunk(int c, uint32_t wsm, int tid) {
    int p = c / NF, f = c - p * NF;
    const int big = (p != 1);
    int cs = big ? CS_BIG : CS_SM;
    const float* g = g_Wp + pass_base(p) + f * cs + tid * 4;
    uint32_t dst = wsm + (c & (NSTG - 1)) * 16384 + tid * 16;
    if (big) {
        asm volatile("cp.async.cg.shared.global [%0], [%1], 16;"
                     :: "r"(dst), "l"(g) : "memory");
        asm volatile("cp.async.cg.shared.global [%0], [%1], 16;"
                     :: "r"(dst + 8192), "l"(g + 2048) : "memory");
    } else if (tid < 256) {
        asm volatile("cp.async.cg.shared.global [%0], [%1], 16;"
                     :: "r"(dst), "l"(g) : "memory");
    }
    asm volatile("cp.async.commit_group;" ::: "memory");
}

// ---------------- epilogue helpers ----------------
__device__ __forceinline__ void store_acc(float* H1s, const float acc[2][4][4],
                                          int mb, int nbb, int tq, int tr) {
    #pragma unroll
    for (int mf = 0; mf < 2; ++mf)
        #pragma unroll
        for (int nb = 0; nb < 4; ++nb) {
            int r0 = mb + mf * 16 + tq;
            int col = nbb + nb * 8 + tr * 2;
            *reinterpret_cast<float2*>(&H1s[r0 * 132 + col]) =
                make_float2(acc[mf][nb][0], acc[mf][nb][1]);
            *reinterpret_cast<float2*>(&H1s[(r0 + 8) * 132 + col]) =
                make_float2(acc[mf][nb][2], acc[mf][nb][3]);
        }
}

__device__ __forceinline__ void write_out(float* __restrict__ out, const float* H1s,
                                          int b0, int colbase, int tid) {
    #pragma unroll
    for (int i = 0; i < 2; ++i) {
        int idx = tid + i * NTHR;         // 0..1023
        int bl = idx >> 7, h = idx & 127;
        float s = 0.0f;
        #pragma unroll
        for (int d = 0; d < 16; ++d) s += H1s[(bl * 16 + d) * 132 + h];
        out[(size_t)(b0 + bl) * 256 + colbase + h] = s;
    }
}

// ---------------- main kernel ----------------
// 256 CTAs, M=128 rows (8 batches x 16 d) per CTA, N=128 (HOUT).
// 16 warps as 4(m)x4(n): warp tile 32x32.
__global__ __launch_bounds__(NTHR, 1)
void cin_kernel(const float* __restrict__ x, float* __restrict__ out) {
    extern __shared__ char smem[];
    float* Xs  = reinterpret_cast<float*>(smem + OFF_X);    // [128][40], col 39 = 0
    float* H1s = reinterpret_cast<float*>(smem + OFF_H1);   // [128][132]
    char*  wbuf = smem + OFF_B;
    const uint32_t wsm = smem_u32(wbuf);

    const int tid = threadIdx.x;
    const int lane = tid & 31, w = tid >> 5;
    const int tq = lane >> 2, tr = lane & 3;
    const int wm = w & 3, wn = w >> 2;
    const int mb = wm * 32, nbb = wn * 32;

    // ---- load x tile: row bd = b_loc*16 + d, col f ----
    const int b0 = blockIdx.x * 8;
    const float* xg = x + (size_t)b0 * (F0V * DDIM);
    for (int idx = tid; idx < F0V * 128; idx += NTHR) {
        int f = idx >> 7, row = idx & 127;
        Xs[row * 40 + f] = xg[(row >> 4) * (F0V * DDIM) + f * DDIM + (row & 15)];
    }
    if (tid < 128) Xs[tid * 40 + 39] = 0.0f;
    __syncthreads();

    float acc[2][4][4];
    #pragma unroll
    for (int a = 0; a < 2; ++a)
        #pragma unroll
        for (int b = 0; b < 4; ++b)
            #pragma unroll
            for (int e = 0; e < 4; ++e) acc[a][b][e] = 0.0f;

    float hf[2][4][4];   // [mfrag][kstep][elem] h-window fragments (fp32)

    // prologue: fill NSTG-1 pipeline stages
    prefetch_chunk(0, wsm, tid);
    prefetch_chunk(1, wsm, tid);
    prefetch_chunk(2, wsm, tid);
    int c = 0;

    for (int p = 0; p < NPASS; ++p) {
        const float* src = (p < 2) ? Xs : H1s;
        const int stride = (p < 2) ? 40 : 132;
        const int qb = (p == 0) ? 0 : ((p == 1) ? 32 : 32 * (p - 2));
        const int nks = (p == 1) ? 1 : 4;

        // load h-window fragments (reused across all 39 f-chunks of the pass)
        #pragma unroll
        for (int mf = 0; mf < 2; ++mf)
            #pragma unroll
            for (int ks = 0; ks < 4; ++ks)
                if (ks < nks)
                    #pragma unroll
                    for (int e = 0; e < 4; ++e)
                        hf[mf][ks][e] =
                            src[(mb + mf * 16 + tq + 8 * (e & 1)) * stride +
                                qb + ks * 8 + tr + 4 * (e >> 1)];

        for (int f = 0; f < NF; ++f) {
            // chunk-c data was fetched 3 iterations ago -> wait is cheap
            asm volatile("cp.async.wait_group 2;" ::: "memory");
            __syncthreads();
            // prefetch c+3 into buffer (c+3)%4: its last readers (chunk c-1)
            // finished before the barrier above.
            if (c + 3 < NCHUNK) prefetch_chunk(c + 3, wsm, tid);

            const char* bp = wbuf + (c & (NSTG - 1)) * 16384;

            // a_f = x0[row][f] for this warp's rows
            float af0[2], af1[2];
            #pragma unroll
            for (int mf = 0; mf < 2; ++mf) {
                af0[mf] = Xs[(mb + mf * 16 + tq) * 40 + f];
                af1[mf] = Xs[(mb + mf * 16 + tq + 8) * 40 + f];
            }

            if (p != 1) {
                const float4* bt = reinterpret_cast<const float4*>(bp);
                #pragma unroll
                for (int ks2 = 0; ks2 < 2; ++ks2) {
                    float4 bv[4];
                    #pragma unroll
                    for (int nb = 0; nb < 4; ++nb)
                        bv[nb] = bt[((wn * 4 + nb) * 2 + ks2) * 32 + lane];
                    #pragma unroll
                    for (int h2 = 0; h2 < 2; ++h2) {
                        const int ks = ks2 * 2 + h2;
                        uint32_t a[2][4];
                        #pragma unroll
                        for (int mf = 0; mf < 2; ++mf) {
                            a[mf][0] = f2tf(af0[mf] * hf[mf][ks][0]);
                            a[mf][1] = f2tf(af1[mf] * hf[mf][ks][1]);
                            a[mf][2] = f2tf(af0[mf] * hf[mf][ks][2]);
                            a[mf][3] = f2tf(af1[mf] * hf[mf][ks][3]);
                        }
                        #pragma unroll
                        for (int mf = 0; mf < 2; ++mf)
                            #pragma unroll
                            for (int nb = 0; nb < 4; ++nb)
                                mma_tf32(acc[mf][nb], a[mf],
                                         h2 ? __float_as_uint(bv[nb].z) : __float_as_uint(bv[nb].x),
                                         h2 ? __float_as_uint(bv[nb].w) : __float_as_uint(bv[nb].y));
                    }
                }
            } else {
                const float2* bt = reinterpret_cast<const float2*>(bp);
                float2 bv[4];
                #pragma unroll
                for (int nb = 0; nb < 4; ++nb)
                    bv[nb] = bt[(wn * 4 + nb) * 32 + lane];
                uint32_t a[2][4];
                #pragma unroll
                for (int mf = 0; mf < 2; ++mf) {
                    a[mf][0] = f2tf(af0[mf] * hf[mf][0][0]);
                    a[mf][1] = f2tf(af1[mf] * hf[mf][0][1]);
                    a[mf][2] = f2tf(af0[mf] * hf[mf][0][2]);
                    a[mf][3] = f2tf(af1[mf] * hf[mf][0][3]);
                }
                #pragma unroll
                for (int mf = 0; mf < 2; ++mf)
                    #pragma unroll
                    for (int nb = 0; nb < 4; ++nb)
                        mma_tf32(acc[mf][nb], a[mf],
                                 __float_as_uint(bv[nb].x), __float_as_uint(bv[nb].y));
            }
            ++c;
        }

        if (p == 1) {
            // layer-1 done: D1 -> H1s, emit layer-1 output, reset acc
            __syncthreads();
            store_acc(H1s, acc, mb, nbb, tq, tr);
            __syncthreads();
            write_out(out, H1s, b0, 0, tid);
            #pragma unroll
            for (int a = 0; a < 2; ++a)
                #pragma unroll
                for (int b = 0; b < 4; ++b)
                    #pragma unroll
                    for (int e = 0; e < 4; ++e) acc[a][b][e] = 0.0f;
        }
    }

    // layer-2 epilogue
    __syncthreads();
    store_acc(H1s, acc, mb, nbb, tq, tr);
    __syncthreads();
    write_out(out, H1s, b0, 128, tid);
}

// ---------------- launch ----------------
extern "C" void kernel_launch(void* const* d_in, const int* in_sizes, int n_in,
                              void* d_out, int out_size) {
    const float* x = nullptr;
    const float* W0 = nullptr;
    const float* W1 = nullptr;
    for (int i = 0; i < n_in; ++i) {
        if (in_sizes[i] == NB * F0V * DDIM)  x  = (const float*)d_in[i];
        else if (in_sizes[i] == 128 * P0)    W0 = (const float*)d_in[i];
        else if (in_sizes[i] == 128 * P1)    W1 = (const float*)d_in[i];
    }
    prep_kernel<<<512, 256>>>(W0, W1);
    cudaFuncSetAttribute(cin_kernel, cudaFuncAttributeMaxDynamicSharedMemorySize, SMEM_TOTAL);
    cin_kernel<<<256, NTHR, SMEM_TOTAL>>>(x, (float*)d_out);
}

// round 9
// speedup vs baseline: 1.0677x; 1.0677x over previous
#include <cuda_runtime.h>
#include <cstdint>

// ---------------- problem constants ----------------
#define NB     2048
#define F0V    39
#define DDIM   16
#define P0     1521
#define P1     4992

// chunk schedule: 6 passes x 39 f-chunks
//  pass 0: layer1, q-window [0,32),  Kc=32
//  pass 1: layer1, q-window [32,40), Kc=8  (q=39 zero-padded)
//  pass 2-5: layer2, q-window [32w,32w+32), Kc=32
#define NPASS  6
#define NF     39
#define NCHUNK (NPASS * NF)      // 234
#define CS_BIG 4096              // floats per Kc=32 W chunk (128n x 32k)
#define CS_SM  1024              // floats per Kc=8 chunk
#define WP_TOTAL (NF * CS_BIG * 5 + NF * CS_SM)   // 838656 floats

#define NTHR   512
#define NSTG   8                 // cp.async pipeline stages (16KB each)

// ---------------- smem layout (bytes) ----------------
#define OFF_X    0               // 128 x 40 fp32 = 20480
#define OFF_H1   20480           // 128 x 132 fp32 = 67584
#define OFF_B    88064           // NSTG x 16384 W buffers
#define SMEM_TOTAL (OFF_B + NSTG * 16384)   // 219136

__device__ float g_Wp[WP_TOTAL];

// ---------------- helpers ----------------
__device__ __forceinline__ uint32_t smem_u32(const void* p) {
    uint32_t a;
    asm("{ .reg .u64 t; cvta.to.shared.u64 t, %1; cvt.u32.u64 %0, t; }" : "=r"(a) : "l"(p));
    return a;
}
__device__ __forceinline__ uint32_t f2tf(float x) {
    uint32_t r;
    asm("cvt.rna.tf32.f32 %0, %1;" : "=r"(r) : "f"(x));
    return r;
}
__device__ __forceinline__ void mma_tf32(float* c, const uint32_t* a, uint32_t b0, uint32_t b1) {
    asm volatile(
        "mma.sync.aligned.m16n8k8.row.col.f32.tf32.tf32.f32 "
        "{%0,%1,%2,%3},{%4,%5,%6,%7},{%8,%9},{%0,%1,%2,%3};"
        : "+f"(c[0]), "+f"(c[1]), "+f"(c[2]), "+f"(c[3])
        : "r"(a[0]), "r"(a[1]), "r"(a[2]), "r"(a[3]), "r"(b0), "r"(b1));
}

__device__ __forceinline__ int pass_base(int p) {
    if (p == 0) return 0;
    if (p == 1) return NF * CS_BIG;
    return NF * CS_BIG + NF * CS_SM + (p - 2) * NF * CS_BIG;
}

// ---------------- prepass: W -> tf32 fragment-packed layout ----------------
// Kc=32 chunk layout: float4[nbg(16)][ks2(2)][lane(32)]:
//   .x=b0(ks=2ks2) .y=b1(ks=2ks2) .z=b0(ks=2ks2+1) .w=b1(ks=2ks2+1)
//   b0: k = 8*ks + lane%4 ; b1: k = 8*ks + lane%4 + 4 ; n = nbg*8 + lane/4
// Kc=8 chunk layout: float2[nbg(16)][lane(32)] = {b0, b1}
__global__ void prep_kernel(const float* __restrict__ W0, const float* __restrict__ W1) {
    for (int idx = blockIdx.x * blockDim.x + threadIdx.x; idx < WP_TOTAL;
         idx += gridDim.x * blockDim.x) {
        int p, rem;
        if (idx < NF * CS_BIG) { p = 0; rem = idx; }
        else if (idx < NF * CS_BIG + NF * CS_SM) { p = 1; rem = idx - NF * CS_BIG; }
        else {
            int j = idx - (NF * CS_BIG + NF * CS_SM);
            p = 2 + j / (NF * CS_BIG);
            rem = j % (NF * CS_BIG);
        }
        int cs = (p == 1) ? CS_SM : CS_BIG;
        int f = rem / cs, r = rem - f * cs;
        int n, kl;
        if (p == 1) {
            int q2 = r >> 1, comp = r & 1;
            int lane = q2 & 31, nbg = q2 >> 5;
            kl = comp * 4 + (lane & 3);
            n = nbg * 8 + (lane >> 2);
        } else {
            int q4 = r >> 2, comp = r & 3;
            int lane = q4 & 31, ks2 = (q4 >> 5) & 1, nbg = q4 >> 6;
            kl = ks2 * 16 + comp * 4 + (lane & 3);
            n = nbg * 8 + (lane >> 2);
        }
        float v;
        if (p == 0) {
            v = W0[n * P0 + f * F0V + kl];                 // q = kl < 32 < 39
        } else if (p == 1) {
            int q = 32 + kl;
            v = (q < F0V) ? W0[n * P0 + f * F0V + q] : 0.0f;
        } else {
            int q = 32 * (p - 2) + kl;
            v = W1[n * P1 + f * 128 + q];
        }
        g_Wp[idx] = __uint_as_float(f2tf(v));
    }
}

// ---------------- cp.async W prefetch (512 threads) ----------------
__device__ __forceinline__ void prefetch_chunk(int c, uint32_t wsm, int tid) {
    int p = c / NF, f = c - p * NF;
    const int big = (p != 1);
    int cs = big ? CS_BIG : CS_SM;
    const float* g = g_Wp + pass_base(p) + f * cs + tid * 4;
    uint32_t dst = wsm + (c & (NSTG - 1)) * 16384 + tid * 16;
    if (big) {
        asm volatile("cp.async.cg.shared.global [%0], [%1], 16;"
                     :: "r"(dst), "l"(g) : "memory");
        asm volatile("cp.async.cg.shared.global [%0], [%1], 16;"
                     :: "r"(dst + 8192), "l"(g + 2048) : "memory");
    } else if (tid < 256) {
        asm volatile("cp.async.cg.shared.global [%0], [%1], 16;"
                     :: "r"(dst), "l"(g) : "memory");
    }
    asm volatile("cp.async.commit_group;" ::: "memory");
}

// ---------------- epilogue helpers ----------------
__device__ __forceinline__ void store_acc(float* H1s, const float acc[2][4][4],
                                          int mb, int nbb, int tq, int tr) {
    #pragma unroll
    for (int mf = 0; mf < 2; ++mf)
        #pragma unroll
        for (int nb = 0; nb < 4; ++nb) {
            int r0 = mb + mf * 16 + tq;
            int col = nbb + nb * 8 + tr * 2;
            *reinterpret_cast<float2*>(&H1s[r0 * 132 + col]) =
                make_float2(acc[mf][nb][0], acc[mf][nb][1]);
            *reinterpret_cast<float2*>(&H1s[(r0 + 8) * 132 + col]) =
                make_float2(acc[mf][nb][2], acc[mf][nb][3]);
        }
}

__device__ __forceinline__ void write_out(float* __restrict__ out, const float* H1s,
                                          int b0, int colbase, int tid) {
    #pragma unroll
    for (int i = 0; i < 2; ++i) {
        int idx = tid + i * NTHR;         // 0..1023
        int bl = idx >> 7, h = idx & 127;
        float s = 0.0f;
        #pragma unroll
        for (int d = 0; d < 16; ++d) s += H1s[(bl * 16 + d) * 132 + h];
        out[(size_t)(b0 + bl) * 256 + colbase + h] = s;
    }
}

// ---------------- main kernel ----------------
// 256 CTAs, M=128 rows (8 batches x 16 d) per CTA, N=128 (HOUT).
// 16 warps as 4(m)x4(n): warp tile 32x32.
// Per chunk: t = H_tf32 x W_f^T (HMMA, A pass-resident in regs),
//            acc += diag(x_f) * t (FFMA). No per-chunk CVT.
__global__ __launch_bounds__(NTHR, 1)
void cin_kernel(const float* __restrict__ x, float* __restrict__ out) {
    extern __shared__ char smem[];
    float* Xs  = reinterpret_cast<float*>(smem + OFF_X);    // [128][40], col 39 = 0
    float* H1s = reinterpret_cast<float*>(smem + OFF_H1);   // [128][132]
    char*  wbuf = smem + OFF_B;
    const uint32_t wsm = smem_u32(wbuf);

    const int tid = threadIdx.x;
    const int lane = tid & 31, w = tid >> 5;
    const int tq = lane >> 2, tr = lane & 3;
    const int wm = w & 3, wn = w >> 2;
    const int mb = wm * 32, nbb = wn * 32;

    // ---- load x tile: row bd = b_loc*16 + d, col f ----
    const int b0 = blockIdx.x * 8;
    const float* xg = x + (size_t)b0 * (F0V * DDIM);
    for (int idx = tid; idx < F0V * 128; idx += NTHR) {
        int f = idx >> 7, row = idx & 127;
        Xs[row * 40 + f] = xg[(row >> 4) * (F0V * DDIM) + f * DDIM + (row & 15)];
    }
    if (tid < 128) Xs[tid * 40 + 39] = 0.0f;
    __syncthreads();

    float acc[2][4][4];
    #pragma unroll
    for (int a = 0; a < 2; ++a)
        #pragma unroll
        for (int b = 0; b < 4; ++b)
            #pragma unroll
            for (int e = 0; e < 4; ++e) acc[a][b][e] = 0.0f;

    uint32_t hfT[2][4][4];   // tf32 A-fragments of the h-window (pass-resident)

    // prologue: fill 6 pipeline stages (3 barrier periods of lead)
    for (int c0 = 0; c0 < 6; ++c0) prefetch_chunk(c0, wsm, tid);

    for (int c = 0; c < NCHUNK; ++c) {
        const int p = c / NF, f = c - p * NF;
        const int big = (p != 1);

        if ((c & 1) == 0) {
            // chunks c, c+1 were committed >= 3 periods ago -> cheap wait
            asm volatile("cp.async.wait_group 4;" ::: "memory");
            __syncthreads();
            // buffers (c+6)&7, (c+7)&7 were last read at chunks c-2, c-1 (pre-barrier)
            if (c + 6 < NCHUNK) prefetch_chunk(c + 6, wsm, tid);
            if (c + 7 < NCHUNK) prefetch_chunk(c + 7, wsm, tid);
        }

        if (c == 2 * NF) {
            // layer-1 done (acc holds D1): D1 -> H1s, emit layer-1 output
            store_acc(H1s, acc, mb, nbb, tq, tr);
            __syncthreads();
            write_out(out, H1s, b0, 0, tid);
            #pragma unroll
            for (int a = 0; a < 2; ++a)
                #pragma unroll
                for (int b = 0; b < 4; ++b)
                    #pragma unroll
                    for (int e = 0; e < 4; ++e) acc[a][b][e] = 0.0f;
        }

        if (f == 0) {
            // pass start: convert h-window fragments to tf32 A-operands (once per pass)
            const float* src = (p < 2) ? Xs : H1s;
            const int stride = (p < 2) ? 40 : 132;
            const int qb = (p == 0) ? 0 : ((p == 1) ? 32 : 32 * (p - 2));
            const int nks = (p == 1) ? 1 : 4;
            #pragma unroll
            for (int mf = 0; mf < 2; ++mf)
                #pragma unroll
                for (int ks = 0; ks < 4; ++ks)
                    if (ks < nks)
                        #pragma unroll
                        for (int e = 0; e < 4; ++e)
                            hfT[mf][ks][e] = f2tf(
                                src[(mb + mf * 16 + tq + 8 * (e & 1)) * stride +
                                    qb + ks * 8 + tr + 4 * (e >> 1)]);
        }

        const char* bp = wbuf + (c & (NSTG - 1)) * 16384;

        // diagonal scale x0[row, f] for this warp's rows
        float af0[2], af1[2];
        #pragma unroll
        for (int mf = 0; mf < 2; ++mf) {
            af0[mf] = Xs[(mb + mf * 16 + tq) * 40 + f];
            af1[mf] = Xs[(mb + mf * 16 + tq + 8) * 40 + f];
        }

        // two n-halves of 16 columns each (keeps temp t at 16 regs)
        #pragma unroll
        for (int nh = 0; nh < 2; ++nh) {
            float t[2][2][4];
            #pragma unroll
            for (int a = 0; a < 2; ++a)
                #pragma unroll
                for (int b = 0; b < 2; ++b)
                    #pragma unroll
                    for (int e = 0; e < 4; ++e) t[a][b][e] = 0.0f;

            if (big) {
                const float4* bt = reinterpret_cast<const float4*>(bp);
                #pragma unroll
                for (int ks2 = 0; ks2 < 2; ++ks2) {
                    float4 bv[2];
                    #pragma unroll
                    for (int nb = 0; nb < 2; ++nb)
                        bv[nb] = bt[((wn * 4 + nh * 2 + nb) * 2 + ks2) * 32 + lane];
                    #pragma unroll
                    for (int h2 = 0; h2 < 2; ++h2) {
                        const int ks = ks2 * 2 + h2;
                        #pragma unroll
                        for (int mf = 0; mf < 2; ++mf)
                            #pragma unroll
                            for (int nb = 0; nb < 2; ++nb)
                                mma_tf32(t[mf][nb], hfT[mf][ks],
                                         h2 ? __float_as_uint(bv[nb].z) : __float_as_uint(bv[nb].x),
                                         h2 ? __float_as_uint(bv[nb].w) : __float_as_uint(bv[nb].y));
                    }
                }
            } else {
                const float2* bt = reinterpret_cast<const float2*>(bp);
                float2 bv[2];
                #pragma unroll
                for (int nb = 0; nb < 2; ++nb)
                    bv[nb] = bt[(wn * 4 + nh * 2 + nb) * 32 + lane];
                #pragma unroll
                for (int mf = 0; mf < 2; ++mf)
                    #pragma unroll
                    for (int nb = 0; nb < 2; ++nb)
                        mma_tf32(t[mf][nb], hfT[mf][0],
                                 __float_as_uint(bv[nb].x), __float_as_uint(bv[nb].y));
            }

            // acc += diag(x_f) * t   (rows {0,1}=tq -> af0, rows {2,3}=tq+8 -> af1)
            #pragma unroll
            for (int mf = 0; mf < 2; ++mf)
                #pragma unroll
                for (int nb = 0; nb < 2; ++nb) {
                    float* A = acc[mf][nh * 2 + nb];
                    A[0] += af0[mf] * t[mf][nb][0];
                    A[1] += af0[mf] * t[mf][nb][1];
                    A[2] += af1[mf] * t[mf][nb][2];
                    A[3] += af1[mf] * t[mf][nb][3];
                }
        }
    }

    // layer-2 epilogue
    __syncthreads();
    store_acc(H1s, acc, mb, nbb, tq, tr);
    __syncthreads();
    write_out(out, H1s, b0, 128, tid);
}

// ---------------- launch ----------------
extern "C" void kernel_launch(void* const* d_in, const int* in_sizes, int n_in,
                              void* d_out, int out_size) {
    const float* x = nullptr;
    const float* W0 = nullptr;
    const float* W1 = nullptr;
    for (int i = 0; i < n_in; ++i) {
        if (in_sizes[i] == NB * F0V * DDIM)  x  = (const float*)d_in[i];
        else if (in_sizes[i] == 128 * P0)    W0 = (const float*)d_in[i];
        else if (in_sizes[i] == 128 * P1)    W1 = (const float*)d_in[i];
    }
    prep_kernel<<<512, 256>>>(W0, W1);
    cudaFuncSetAttribute(cin_kernel, cudaFuncAttributeMaxDynamicSharedMemorySize, SMEM_TOTAL);
    cin_kernel<<<256, NTHR, SMEM_TOTAL>>>(x, (float*)d_out);
}

// round 11
// speedup vs baseline: 1.1377x; 1.0656x over previous
#include <cuda_runtime.h>
#include <cstdint>

// ---------------- problem constants ----------------
#define NB     2048
#define F0V    39
#define DDIM   16
#define P0     1521
#define P1     4992

// chunk schedule: 6 passes x 39 f-chunks
//  pass 0: layer1, q-window [0,32),  Kc=32
//  pass 1: layer1, q-window [32,40), Kc=8  (q=39 zero-padded)
//  pass 2-5: layer2, q-window [32w,32w+32), Kc=32
#define NPASS  6
#define NF     39
#define NCHUNK (NPASS * NF)      // 234
#define CS_BIG 4096              // floats per Kc=32 W chunk (128n x 32k)
#define CS_SM  1024              // floats per Kc=8 chunk
#define WP_TOTAL (NF * CS_BIG * 5 + NF * CS_SM)   // 838656 floats

#define NTHR   256               // 2 CTAs / SM
#define NSTG   4                 // cp.async pipeline stages (16KB each)
#define MROWS  64                // rows (4 batches x 16 d) per CTA

// ---------------- smem layout (bytes) ----------------
#define OFF_X    0               // 64 x 40 fp32 = 10240
#define OFF_H1   10240           // 64 x 132 fp32 = 33792
#define OFF_B    44032           // NSTG x 16384 W buffers
#define SMEM_TOTAL (OFF_B + NSTG * 16384)   // 109568  (x2 CTAs = 219136/SM)

__device__ float g_Wp[WP_TOTAL];

// ---------------- helpers ----------------
__device__ __forceinline__ uint32_t smem_u32(const void* p) {
    uint32_t a;
    asm("{ .reg .u64 t; cvta.to.shared.u64 t, %1; cvt.u32.u64 %0, t; }" : "=r"(a) : "l"(p));
    return a;
}
__device__ __forceinline__ uint32_t f2tf(float x) {
    uint32_t r;
    asm("cvt.rna.tf32.f32 %0, %1;" : "=r"(r) : "f"(x));
    return r;
}
// accumulate form: d == c (in place)
__device__ __forceinline__ void mma_tf32(float* c, const uint32_t* a, uint32_t b0, uint32_t b1) {
    asm volatile(
        "mma.sync.aligned.m16n8k8.row.col.f32.tf32.tf32.f32 "
        "{%0,%1,%2,%3},{%4,%5,%6,%7},{%8,%9},{%0,%1,%2,%3};"
        : "+f"(c[0]), "+f"(c[1]), "+f"(c[2]), "+f"(c[3])
        : "r"(a[0]), "r"(a[1]), "r"(a[2]), "r"(a[3]), "r"(b0), "r"(b1));
}
// init form: d = a*b + 0 (C const-folds to RZ; kills per-chunk zero-init MOVs)
__device__ __forceinline__ void mma_tf32_zero(float* d, const uint32_t* a, uint32_t b0, uint32_t b1) {
    asm volatile(
        "mma.sync.aligned.m16n8k8.row.col.f32.tf32.tf32.f32 "
        "{%0,%1,%2,%3},{%4,%5,%6,%7},{%8,%9},{%10,%10,%10,%10};"
        : "=f"(d[0]), "=f"(d[1]), "=f"(d[2]), "=f"(d[3])
        : "r"(a[0]), "r"(a[1]), "r"(a[2]), "r"(a[3]), "r"(b0), "r"(b1), "f"(0.0f));
}
// packed fp32x2 ops (plain sm_100+ PTX; NOT arch-suffix gated)
__device__ __forceinline__ uint64_t pack2(float lo, float hi) {
    uint64_t r; asm("mov.b64 %0, {%1,%2};" : "=l"(r) : "f"(lo), "f"(hi)); return r;
}
__device__ __forceinline__ uint64_t pack2s(float v) {
    uint64_t r; asm("mov.b64 %0, {%1,%1};" : "=l"(r) : "f"(v)); return r;
}
__device__ __forceinline__ void unpack2(uint64_t v, float& lo, float& hi) {
    asm("mov.b64 {%0,%1}, %2;" : "=f"(lo), "=f"(hi) : "l"(v));
}
__device__ __forceinline__ void ffma2(uint64_t& c, uint64_t a, uint64_t b) {
    asm("fma.rn.f32x2 %0, %1, %2, %0;" : "+l"(c) : "l"(a), "l"(b));
}

__device__ __forceinline__ int pass_base(int p) {
    if (p == 0) return 0;
    if (p == 1) return NF * CS_BIG;
    return NF * CS_BIG + NF * CS_SM + (p - 2) * NF * CS_BIG;
}

// ---------------- prepass: W -> tf32 fragment-packed layout ----------------
// Kc=32 chunk layout: float4[nbg(16)][ks2(2)][lane(32)]:
//   .x=b0(ks=2ks2) .y=b1(ks=2ks2) .z=b0(ks=2ks2+1) .w=b1(ks=2ks2+1)
//   b0: k = 8*ks + lane%4 ; b1: k = 8*ks + lane%4 + 4 ; n = nbg*8 + lane/4
// Kc=8 chunk layout: float2[nbg(16)][lane(32)] = {b0, b1}
__global__ void prep_kernel(const float* __restrict__ W0, const float* __restrict__ W1) {
    for (int idx = blockIdx.x * blockDim.x + threadIdx.x; idx < WP_TOTAL;
         idx += gridDim.x * blockDim.x) {
        int p, rem;
        if (idx < NF * CS_BIG) { p = 0; rem = idx; }
        else if (idx < NF * CS_BIG + NF * CS_SM) { p = 1; rem = idx - NF * CS_BIG; }
        else {
            int j = idx - (NF * CS_BIG + NF * CS_SM);
            p = 2 + j / (NF * CS_BIG);
            rem = j % (NF * CS_BIG);
        }
        int cs = (p == 1) ? CS_SM : CS_BIG;
        int f = rem / cs, r = rem - f * cs;
        int n, kl;
        if (p == 1) {
            int q2 = r >> 1, comp = r & 1;
            int lane = q2 & 31, nbg = q2 >> 5;
            kl = comp * 4 + (lane & 3);
            n = nbg * 8 + (lane >> 2);
        } else {
            int q4 = r >> 2, comp = r & 3;
            int lane = q4 & 31, ks2 = (q4 >> 5) & 1, nbg = q4 >> 6;
            kl = ks2 * 16 + comp * 4 + (lane & 3);
            n = nbg * 8 + (lane >> 2);
        }
        float v;
        if (p == 0) {
            v = W0[n * P0 + f * F0V + kl];                 // q = kl < 32 < 39
        } else if (p == 1) {
            int q = 32 + kl;
            v = (q < F0V) ? W0[n * P0 + f * F0V + q] : 0.0f;
        } else {
            int q = 32 * (p - 2) + kl;
            v = W1[n * P1 + f * 128 + q];
        }
        g_Wp[idx] = __uint_as_float(f2tf(v));
    }
}

// ---------------- cp.async W prefetch (256 threads) ----------------
__device__ __forceinline__ void prefetch_chunk(int c, uint32_t wsm, int tid) {
    int p = c / NF, f = c - p * NF;
    const int big = (p != 1);
    int cs = big ? CS_BIG : CS_SM;
    const float* g = g_Wp + pass_base(p) + f * cs + tid * 4;
    uint32_t dst = wsm + (c & (NSTG - 1)) * 16384 + tid * 16;
    if (big) {
        #pragma unroll
        for (int i = 0; i < 4; ++i)
            asm volatile("cp.async.cg.shared.global [%0], [%1], 16;"
                         :: "r"(dst + i * 4096), "l"(g + i * 1024) : "memory");
    } else {
        asm volatile("cp.async.cg.shared.global [%0], [%1], 16;"
                     :: "r"(dst), "l"(g) : "memory");
    }
    asm volatile("cp.async.commit_group;" ::: "memory");
}

// ---------------- epilogue helpers ----------------
__device__ __forceinline__ void store_acc(float* H1s, const uint64_t acc2[2][4][2],
                                          int mb, int nbb, int tq, int tr) {
    #pragma unroll
    for (int mf = 0; mf < 2; ++mf)
        #pragma unroll
        for (int nb = 0; nb < 4; ++nb) {
            float a0, a1, a2, a3;
            unpack2(acc2[mf][nb][0], a0, a1);
            unpack2(acc2[mf][nb][1], a2, a3);
            int r0 = mb + mf * 16 + tq;
            int col = nbb + nb * 8 + tr * 2;
            *reinterpret_cast<float2*>(&H1s[r0 * 132 + col]) = make_float2(a0, a1);
            *reinterpret_cast<float2*>(&H1s[(r0 + 8) * 132 + col]) = make_float2(a2, a3);
        }
}

__device__ __forceinline__ void write_out(float* __restrict__ out, const float* H1s,
                                          int b0, int colbase, int tid) {
    #pragma unroll
    for (int i = 0; i < 2; ++i) {
        int idx = tid + i * NTHR;         // 0..511
        int bl = idx >> 7, h = idx & 127;
        float s = 0.0f;
        #pragma unroll
        for (int d = 0; d < 16; ++d) s += H1s[(bl * 16 + d) * 132 + h];
        out[(size_t)(b0 + bl) * 256 + colbase + h] = s;
    }
}

// ---------------- main kernel ----------------
// 512 CTAs (2/SM), M=64 rows (4 batches x 16 d) per CTA, N=128 (HOUT).
// 8 warps as 2(m)x4(n): warp tile 32x32.
// Per chunk: t = H_tf32 x W_f^T (HMMA, A pass-resident in regs, first k-step
// writes t with C=0), acc += diag(x_f)*t via packed fma.rn.f32x2.
__global__ __launch_bounds__(NTHR, 2)
void cin_kernel(const float* __restrict__ x, float* __restrict__ out) {
    extern __shared__ char smem[];
    float* Xs  = reinterpret_cast<float*>(smem + OFF_X);    // [64][40], col 39 = 0
    float* H1s = reinterpret_cast<float*>(smem + OFF_H1);   // [64][132]
    char*  wbuf = smem + OFF_B;
    const uint32_t wsm = smem_u32(wbuf);

    const int tid = threadIdx.x;
    const int lane = tid & 31, w = tid >> 5;
    const int tq = lane >> 2, tr = lane & 3;
    const int wm = w & 1, wn = w >> 1;
    const int mb = wm * 32, nbb = wn * 32;

    // ---- load x tile: row bd = b_loc*16 + d, col f ----
    const int b0 = blockIdx.x * 4;
    const float* xg = x + (size_t)b0 * (F0V * DDIM);
    for (int idx = tid; idx < F0V * MROWS; idx += NTHR) {
        int f = idx >> 6, row = idx & 63;
        Xs[row * 40 + f] = xg[(row >> 4) * (F0V * DDIM) + f * DDIM + (row & 15)];
    }
    if (tid < MROWS) Xs[tid * 40 + 39] = 0.0f;
    __syncthreads();

    uint64_t acc2[2][4][2];   // packed fp32 pairs
    #pragma unroll
    for (int a = 0; a < 2; ++a)
        #pragma unroll
        for (int b = 0; b < 4; ++b) { acc2[a][b][0] = 0ull; acc2[a][b][1] = 0ull; }

    uint32_t hfT[2][4][4];   // tf32 A-fragments of the h-window (pass-resident)

    // prologue: fill first 2 pipeline stages (1 barrier period of lead)
    prefetch_chunk(0, wsm, tid);
    prefetch_chunk(1, wsm, tid);

    for (int c = 0; c < NCHUNK; ++c) {
        const int p = c / NF, f = c - p * NF;
        const int big = (p != 1);

        if ((c & 1) == 0) {
            asm volatile("cp.async.wait_group 0;" ::: "memory");
            __syncthreads();
            // stages (c+2)&3, (c+3)&3 were last read in period c-2 (pre-barrier)
            if (c + 2 < NCHUNK) prefetch_chunk(c + 2, wsm, tid);
            if (c + 3 < NCHUNK) prefetch_chunk(c + 3, wsm, tid);
        }

        if (c == 2 * NF) {
            // layer-1 done (acc holds D1): D1 -> H1s, emit layer-1 output
            store_acc(H1s, acc2, mb, nbb, tq, tr);
            __syncthreads();
            write_out(out, H1s, b0, 0, tid);
            #pragma unroll
            for (int a = 0; a < 2; ++a)
                #pragma unroll
                for (int b = 0; b < 4; ++b) { acc2[a][b][0] = 0ull; acc2[a][b][1] = 0ull; }
        }

        if (f == 0) {
            // pass start: convert h-window fragments to tf32 A-operands (once per pass)
            const float* src = (p < 2) ? Xs : H1s;
            const int stride = (p < 2) ? 40 : 132;
            const int qb = (p == 0) ? 0 : ((p == 1) ? 32 : 32 * (p - 2));
            const int nks = (p == 1) ? 1 : 4;
            #pragma unroll
            for (int mf = 0; mf < 2; ++mf)
                #pragma unroll
                for (int ks = 0; ks < 4; ++ks)
                    if (ks < nks)
                        #pragma unroll
                        for (int e = 0; e < 4; ++e)
                            hfT[mf][ks][e] = f2tf(
                                src[(mb + mf * 16 + tq + 8 * (e & 1)) * stride +
                                    qb + ks * 8 + tr + 4 * (e >> 1)]);
        }

        const char* bp = wbuf + (c & (NSTG - 1)) * 16384;

        // diagonal scale x0[row, f], packed {v,v} for f32x2 updates
        uint64_t pa0[2], pa1[2];
        #pragma unroll
        for (int mf = 0; mf < 2; ++mf) {
            pa0[mf] = pack2s(Xs[(mb + mf * 16 + tq) * 40 + f]);
            pa1[mf] = pack2s(Xs[(mb + mf * 16 + tq + 8) * 40 + f]);
        }

        // two n-halves of 16 columns each (keeps temp t at 16 regs)
        #pragma unroll
        for (int nh = 0; nh < 2; ++nh) {
            float t[2][2][4];

            if (big) {
                const float4* bt = reinterpret_cast<const float4*>(bp);
                #pragma unroll
                for (int ks2 = 0; ks2 < 2; ++ks2) {
                    float4 bv[2];
                    #pragma unroll
                    for (int nb = 0; nb < 2; ++nb)
                        bv[nb] = bt[((wn * 4 + nh * 2 + nb) * 2 + ks2) * 32 + lane];
                    #pragma unroll
                    for (int h2 = 0; h2 < 2; ++h2) {
                        const int ks = ks2 * 2 + h2;
                        #pragma unroll
                        for (int mf = 0; mf < 2; ++mf)
                            #pragma unroll
                            for (int nb = 0; nb < 2; ++nb) {
                                uint32_t bb0 = h2 ? __float_as_uint(bv[nb].z) : __float_as_uint(bv[nb].x);
                                uint32_t bb1 = h2 ? __float_as_uint(bv[nb].w) : __float_as_uint(bv[nb].y);
                                if (ks == 0)
                                    mma_tf32_zero(t[mf][nb], hfT[mf][0], bb0, bb1);
                                else
                                    mma_tf32(t[mf][nb], hfT[mf][ks], bb0, bb1);
                            }
                    }
                }
            } else {
                const float2* bt = reinterpret_cast<const float2*>(bp);
                #pragma unroll
                for (int nb = 0; nb < 2; ++nb) {
                    float2 bv = bt[(wn * 4 + nh * 2 + nb) * 32 + lane];
                    #pragma unroll
                    for (int mf = 0; mf < 2; ++mf)
                        mma_tf32_zero(t[mf][nb], hfT[mf][0],
                                      __float_as_uint(bv.x), __float_as_uint(bv.y));
                }
            }

            // acc += diag(x_f) * t   (rows {0,1}=tq -> pa0, rows {2,3}=tq+8 -> pa1)
            #pragma unroll
            for (int mf = 0; mf < 2; ++mf)
                #pragma unroll
                for (int nb = 0; nb < 2; ++nb) {
                    ffma2(acc2[mf][nh * 2 + nb][0], pa0[mf],
                          pack2(t[mf][nb][0], t[mf][nb][1]));
                    ffma2(acc2[mf][nh * 2 + nb][1], pa1[mf],
                          pack2(t[mf][nb][2], t[mf][nb][3]));
                }
        }
    }

    // layer-2 epilogue
    __syncthreads();
    store_acc(H1s, acc2, mb, nbb, tq, tr);
    __syncthreads();
    write_out(out, H1s, b0, 128, tid);
}

// ---------------- launch ----------------
extern "C" void kernel_launch(void* const* d_in, const int* in_sizes, int n_in,
                              void* d_out, int out_size) {
    const float* x = nullptr;
    const float* W0 = nullptr;
    const float* W1 = nullptr;
    for (int i = 0; i < n_in; ++i) {
        if (in_sizes[i] == NB * F0V * DDIM)  x  = (const float*)d_in[i];
        else if (in_sizes[i] == 128 * P0)    W0 = (const float*)d_in[i];
        else if (in_sizes[i] == 128 * P1)    W1 = (const float*)d_in[i];
    }
    prep_kernel<<<512, 256>>>(W0, W1);
    cudaFuncSetAttribute(cin_kernel, cudaFuncAttributeMaxDynamicSharedMemorySize, SMEM_TOTAL);
    cin_kernel<<<512, NTHR, SMEM_TOTAL>>>(x, (float*)d_out);
}

// round 14
// speedup vs baseline: 1.4889x; 1.3087x over previous
#include <cuda_runtime.h>
#include <cuda_fp16.h>
#include <cstdint>

// ---------------- problem constants ----------------
#define NB     2048
#define F0V    39
#define DDIM   16
#define P0     1521
#define P1     4992

// chunk schedule (symmetrized layer-1):
//  pass 0: layer1, q-window [0,32), f=0..31 (W0 symmetrized: upper-tri doubled,
//          lower zero). Chunks f>=16 skip k-step 0 (q<16 < f impossible).
//  pass 1: layer1, q-window [32,40), f=0..38, Kc=8 (q=39 zero pad)
//  pass 2-5: layer2, q-window [32w,32w+32), f=0..38
#define NC0    32
#define NC1    39
#define NCL2   156              // 4*39
#define NCHUNK (NC0 + NC1 + NCL2)   // 227
#define L1END  (NC0 + NC1)      // 71

// W storage in packed f16x2 (uint32 units)
#define CSU_BIG 2048            // 128n x 32k halves / 2
#define CSU_SM  512             // 128n x 8k halves / 2
#define BASE_P1 (NC0 * CSU_BIG)             // 65536
#define BASE_P2 (BASE_P1 + NC1 * CSU_SM)    // 85504
#define WPU_TOTAL (BASE_P2 + NCL2 * CSU_BIG) // 404992

#define NTHR   256              // 2 CTAs / SM
#define NSTG   4                // cp.async stages
#define STGB   8192             // bytes per big stage
#define MROWS  64               // rows (4 batches x 16 d) per CTA

// ---------------- smem layout (bytes) ----------------
#define OFF_XT   0              // XsT: 40 x 64 fp32 (permuted) = 10240
#define OFF_H1   10240          // 64 x 132 fp32 = 33792
#define OFF_B    44032          // NSTG x 8192 W buffers
#define SMEM_TOTAL (OFF_B + NSTG * STGB)    // 76800 (x2 CTAs/SM)

__device__ __align__(16) uint32_t g_Wh[WPU_TOTAL];

// ---------------- helpers ----------------
__device__ __forceinline__ uint32_t smem_u32(const void* p) {
    uint32_t a;
    asm("{ .reg .u64 t; cvta.to.shared.u64 t, %1; cvt.u32.u64 %0, t; }" : "=r"(a) : "l"(p));
    return a;
}
// pack two fp32 -> f16x2 {lo=first arg, hi=second arg}. Used identically for A
// and B fragments, so any lo/hi convention is self-consistent in the MMA dot.
__device__ __forceinline__ uint32_t pk16(float lo, float hi) {
    uint32_t r;
    asm("cvt.rn.f16x2.f32 %0, %1, %2;" : "=r"(r) : "f"(hi), "f"(lo));
    return r;
}
// m16n8k16 fp16 MMA, fp32 accum, in place
__device__ __forceinline__ void mma16(float* c, const uint32_t* a, uint32_t b0, uint32_t b1) {
    asm volatile(
        "mma.sync.aligned.m16n8k16.row.col.f32.f16.f16.f32 "
        "{%0,%1,%2,%3},{%4,%5,%6,%7},{%8,%9},{%0,%1,%2,%3};"
        : "+f"(c[0]), "+f"(c[1]), "+f"(c[2]), "+f"(c[3])
        : "r"(a[0]), "r"(a[1]), "r"(a[2]), "r"(a[3]), "r"(b0), "r"(b1));
}
// zero-C form (no per-chunk accumulator init)
__device__ __forceinline__ void mma16z(float* d, const uint32_t* a, uint32_t b0, uint32_t b1) {
    asm volatile(
        "mma.sync.aligned.m16n8k16.row.col.f32.f16.f16.f32 "
        "{%0,%1,%2,%3},{%4,%5,%6,%7},{%8,%9},{%10,%10,%10,%10};"
        : "=f"(d[0]), "=f"(d[1]), "=f"(d[2]), "=f"(d[3])
        : "r"(a[0]), "r"(a[1]), "r"(a[2]), "r"(a[3]), "r"(b0), "r"(b1), "f"(0.0f));
}
// m16n8k8 fp16 MMA, zero-C (pass-1 Kc=8)
__device__ __forceinline__ void mma8z(float* d, const uint32_t* a, uint32_t b0) {
    asm volatile(
        "mma.sync.aligned.m16n8k8.row.col.f32.f16.f16.f32 "
        "{%0,%1,%2,%3},{%4,%5},{%6},{%7,%7,%7,%7};"
        : "=f"(d[0]), "=f"(d[1]), "=f"(d[2]), "=f"(d[3])
        : "r"(a[0]), "r"(a[1]), "r"(b0), "f"(0.0f));
}
// packed fp32x2
__device__ __forceinline__ uint64_t pack2(float lo, float hi) {
    uint64_t r; asm("mov.b64 %0, {%1,%2};" : "=l"(r) : "f"(lo), "f"(hi)); return r;
}
__device__ __forceinline__ uint64_t pack2s(float v) {
    uint64_t r; asm("mov.b64 %0, {%1,%1};" : "=l"(r) : "f"(v)); return r;
}
__device__ __forceinline__ void unpack2(uint64_t v, float& lo, float& hi) {
    asm("mov.b64 {%0,%1}, %2;" : "=f"(lo), "=f"(hi) : "l"(v));
}
__device__ __forceinline__ void ffma2(uint64_t& c, uint64_t a, uint64_t b) {
    asm("fma.rn.f32x2 %0, %1, %2, %0;" : "+l"(c) : "l"(a), "l"(b));
}

// symmetrized W0 value: q>f doubled pair sum, q==f diagonal, q<f (or pad) zero
__device__ __forceinline__ float symv(const float* __restrict__ W0, int n, int f, int q) {
    if (q > 38) return 0.0f;
    if (q > f)  return W0[n * P0 + f * F0V + q] + W0[n * P0 + q * F0V + f];
    if (q == f) return W0[n * P0 + f * F0V + q];
    return 0.0f;
}

// ---------------- prepass: W -> packed f16x2 fragment layout ----------------
// Big chunk (Kc=32): uint4[nbg(16)][lane(32)], components (lane: tq=lane/4, tr=lane%4):
//   comp c: k_even = (c>>1)*16 + (c&1)*8 + 2*tr ; pair (k_even, k_even+1); n = nbg*8+tq
// Small chunk (Kc=8): uint32[nbg(16)][lane(32)]: k_even = 2*tr; n = nbg*8+tq
__global__ void prep_kernel(const float* __restrict__ W0, const float* __restrict__ W1) {
    for (int idx = blockIdx.x * blockDim.x + threadIdx.x; idx < WPU_TOTAL;
         idx += gridDim.x * blockDim.x) {
        int p, f, u;
        if (idx < BASE_P1)      { p = 0; f = idx / CSU_BIG; u = idx % CSU_BIG; }
        else if (idx < BASE_P2) { int j = idx - BASE_P1; p = 1; f = j / CSU_SM; u = j % CSU_SM; }
        else {
            int j = idx - BASE_P2; int cc = j / CSU_BIG;
            p = 2 + cc / NC1; f = cc % NC1; u = j % CSU_BIG;
        }
        int n, ke;
        if (p == 1) {
            int lane = u & 31, nbg = u >> 5;
            n = nbg * 8 + (lane >> 2);
            ke = 2 * (lane & 3);
        } else {
            int comp = u & 3, lane = (u >> 2) & 31, nbg = u >> 7;
            n = nbg * 8 + (lane >> 2);
            ke = (comp >> 1) * 16 + (comp & 1) * 8 + 2 * (lane & 3);
        }
        float v0, v1;
        if (p == 0)      { v0 = symv(W0, n, f, ke);      v1 = symv(W0, n, f, ke + 1); }
        else if (p == 1) { v0 = symv(W0, n, f, 32 + ke); v1 = symv(W0, n, f, 33 + ke); }
        else {
            int q = 32 * (p - 2) + ke;
            v0 = W1[n * P1 + f * 128 + q];
            v1 = W1[n * P1 + f * 128 + q + 1];
        }
        g_Wh[idx] = pk16(v0, v1);
    }
}

// ---------------- chunk -> (p, f, base) ----------------
__device__ __forceinline__ void chunk_map(int c, int& p, int& f, uint32_t& base) {
    if (c < NC0)        { p = 0; f = c;        base = (uint32_t)c * CSU_BIG; }
    else if (c < L1END) { p = 1; f = c - NC0;  base = BASE_P1 + (uint32_t)(c - NC0) * CSU_SM; }
    else {
        int j = c - L1END;
        p = 2 + j / NC1; f = j % NC1;
        base = BASE_P2 + (uint32_t)j * CSU_BIG;
    }
}

// ---------------- cp.async W prefetch (256 threads) ----------------
__device__ __forceinline__ void prefetch_chunk(int c, uint32_t wsm, int tid) {
    int p, f; uint32_t base;
    chunk_map(c, p, f, base);
    const uint32_t* g = g_Wh + base;
    uint32_t dst = wsm + (c & (NSTG - 1)) * STGB;
    if (p != 1) {
        asm volatile("cp.async.cg.shared.global [%0], [%1], 16;"
                     :: "r"(dst + tid * 16), "l"(g + tid * 4) : "memory");
        asm volatile("cp.async.cg.shared.global [%0], [%1], 16;"
                     :: "r"(dst + 4096 + tid * 16), "l"(g + 1024 + tid * 4) : "memory");
    } else {
        asm volatile("cp.async.ca.shared.global [%0], [%1], 8;"
                     :: "r"(dst + tid * 8), "l"(g + tid * 2) : "memory");
    }
    asm volatile("cp.async.commit_group;" ::: "memory");
}

// ---------------- epilogue helpers ----------------
__device__ __forceinline__ void store_acc(float* H1s, const uint64_t acc2[2][4][2],
                                          int mb, int nbb, int tq, int tr) {
    #pragma unroll
    for (int mf = 0; mf < 2; ++mf)
        #pragma unroll
        for (int nb = 0; nb < 4; ++nb) {
            float a0, a1, a2, a3;
            unpack2(acc2[mf][nb][0], a0, a1);
            unpack2(acc2[mf][nb][1], a2, a3);
            int r0 = mb + mf * 16 + tq;
            int col = nbb + nb * 8 + tr * 2;
            *reinterpret_cast<float2*>(&H1s[r0 * 132 + col]) = make_float2(a0, a1);
            *reinterpret_cast<float2*>(&H1s[(r0 + 8) * 132 + col]) = make_float2(a2, a3);
        }
}

__device__ __forceinline__ void write_out(float* __restrict__ out, const float* H1s,
                                          int b0, int colbase, int tid) {
    #pragma unroll
    for (int i = 0; i < 2; ++i) {
        int idx = tid + i * NTHR;         // 0..511
        int bl = idx >> 7, h = idx & 127;
        float s = 0.0f;
        #pragma unroll
        for (int d = 0; d < 16; ++d) s += H1s[(bl * 16 + d) * 132 + h];
        out[(size_t)(b0 + bl) * 256 + colbase + h] = s;
    }
}

// ---------------- main kernel ----------------
// 512 CTAs (2/SM), M=64 rows per CTA, N=128. 8 warps as 2(m)x4(n), tile 32x32.
// Per chunk: t = H_f16 x W_f^T (fp16 HMMA, A pass-resident, zero-C first step),
//            acc += diag(x_f)*t via packed fma.rn.f32x2 (x exact fp32).
__global__ __launch_bounds__(NTHR, 2)
void cin_kernel(const float* __restrict__ x, float* __restrict__ out) {
    extern __shared__ char smem[];
    float* XsT = reinterpret_cast<float*>(smem + OFF_XT);   // permuted x^T [40][64]
    float* H1s = reinterpret_cast<float*>(smem + OFF_H1);   // [64][132]
    char*  wbuf = smem + OFF_B;
    const uint32_t wsm = smem_u32(wbuf);

    const int tid = threadIdx.x;
    const int lane = tid & 31, w = tid >> 5;
    const int tq = lane >> 2, tr = lane & 3;
    const int wm = w & 1, wn = w >> 1;
    const int mb = wm * 32, nbb = wn * 32;

    // ---- build XsT: XsT[((f*2+wm')*8+tq')*4 + j] = x[row=32wm'+8j+tq', f]; f=39 zero ----
    const int b0 = blockIdx.x * 4;
    const float* xg = x + (size_t)b0 * (F0V * DDIM);
    for (int idx = tid; idx < 40 * MROWS; idx += NTHR) {
        int f = idx >> 6, row = idx & 63;
        float v = (f < F0V) ? xg[(row >> 4) * (F0V * DDIM) + f * DDIM + (row & 15)] : 0.0f;
        XsT[(((f << 1) + (row >> 5)) * 8 + (row & 7)) * 4 + ((row >> 3) & 3)] = v;
    }
    __syncthreads();

    uint64_t acc2[2][4][2];
    #pragma unroll
    for (int a = 0; a < 2; ++a)
        #pragma unroll
        for (int b = 0; b < 4; ++b) { acc2[a][b][0] = 0ull; acc2[a][b][1] = 0ull; }

    uint32_t hfT[2][2][4];   // f16x2 A-fragments [mf][ks16][reg], pass-resident

    prefetch_chunk(0, wsm, tid);
    prefetch_chunk(1, wsm, tid);

    for (int c = 0; c < NCHUNK; ++c) {
        int p, f; uint32_t dummy;
        chunk_map(c, p, f, dummy);

        if ((c & 1) == 0) {
            asm volatile("cp.async.wait_group 0;" ::: "memory");
            __syncthreads();
            if (c + 2 < NCHUNK) prefetch_chunk(c + 2, wsm, tid);
            if (c + 3 < NCHUNK) prefetch_chunk(c + 3, wsm, tid);
        }

        if (c == L1END) {
            // layer-1 complete: D1 -> H1s, emit layer-1 output, reset acc
            store_acc(H1s, acc2, mb, nbb, tq, tr);
            __syncthreads();
            write_out(out, H1s, b0, 0, tid);
            #pragma unroll
            for (int a = 0; a < 2; ++a)
                #pragma unroll
                for (int b = 0; b < 4; ++b) { acc2[a][b][0] = 0ull; acc2[a][b][1] = 0ull; }
        }

        if (f == 0) {
            // pass start: build fp16 A-fragments (once per pass)
            if (p < 2) {
                #pragma unroll
                for (int mf = 0; mf < 2; ++mf) {
                    if (p == 0) {
                        #pragma unroll
                        for (int ks = 0; ks < 2; ++ks) {
                            int q0 = ks * 16 + 2 * tr;
                            #pragma unroll
                            for (int half = 0; half < 2; ++half) {
                                int q = q0 + 8 * half;
                                int a0 = (((q << 1) + wm) * 8 + tq) * 4 + 2 * mf;
                                int a1 = ((((q + 1) << 1) + wm) * 8 + tq) * 4 + 2 * mf;
                                hfT[mf][ks][2 * half + 0] = pk16(XsT[a0], XsT[a1]);
                                hfT[mf][ks][2 * half + 1] = pk16(XsT[a0 + 1], XsT[a1 + 1]);
                            }
                        }
                    } else {
                        int q = 32 + 2 * tr;
                        int a0 = (((q << 1) + wm) * 8 + tq) * 4 + 2 * mf;
                        int a1 = ((((q + 1) << 1) + wm) * 8 + tq) * 4 + 2 * mf;
                        hfT[mf][0][0] = pk16(XsT[a0], XsT[a1]);
                        hfT[mf][0][1] = pk16(XsT[a0 + 1], XsT[a1 + 1]);
                    }
                }
            } else {
                const int qb = 32 * (p - 2);
                #pragma unroll
                for (int mf = 0; mf < 2; ++mf)
                    #pragma unroll
                    for (int ks = 0; ks < 2; ++ks) {
                        int r0 = mb + mf * 16 + tq;
                        int q0 = qb + ks * 16 + 2 * tr;
                        hfT[mf][ks][0] = pk16(H1s[r0 * 132 + q0], H1s[r0 * 132 + q0 + 1]);
                        hfT[mf][ks][1] = pk16(H1s[(r0 + 8) * 132 + q0], H1s[(r0 + 8) * 132 + q0 + 1]);
                        hfT[mf][ks][2] = pk16(H1s[r0 * 132 + q0 + 8], H1s[r0 * 132 + q0 + 9]);
                        hfT[mf][ks][3] = pk16(H1s[(r0 + 8) * 132 + q0 + 8], H1s[(r0 + 8) * 132 + q0 + 9]);
                    }
            }
        }

        const char* bp = wbuf + (c & (NSTG - 1)) * STGB;

        // diagonal x0[row, f]: one broadcast LDS.128 per thread
        const float4 afv = *reinterpret_cast<const float4*>(
            XsT + (((f << 1) + wm) * 8 + tq) * 4);
        const uint64_t pa_r0[2] = { pack2s(afv.x), pack2s(afv.z) };   // rows tq (mf 0,1)
        const uint64_t pa_r1[2] = { pack2s(afv.y), pack2s(afv.w) };   // rows tq+8

        if (p != 1) {
            const bool only1 = (p == 0) && (f >= 16);   // symmetrized skip of k-step 0
            const uint4* bt = reinterpret_cast<const uint4*>(bp);
            #pragma unroll
            for (int nh = 0; nh < 2; ++nh) {
                uint4 bv[2];
                #pragma unroll
                for (int nb = 0; nb < 2; ++nb)
                    bv[nb] = bt[(wn * 4 + nh * 2 + nb) * 32 + lane];
                float t[2][2][4];
                #pragma unroll
                for (int mf = 0; mf < 2; ++mf)
                    #pragma unroll
                    for (int nb = 0; nb < 2; ++nb) {
                        if (only1) {
                            mma16z(t[mf][nb], hfT[mf][1], bv[nb].z, bv[nb].w);
                        } else {
                            mma16z(t[mf][nb], hfT[mf][0], bv[nb].x, bv[nb].y);
                            mma16(t[mf][nb], hfT[mf][1], bv[nb].z, bv[nb].w);
                        }
                    }
                #pragma unroll
                for (int mf = 0; mf < 2; ++mf)
                    #pragma unroll
                    for (int nb = 0; nb < 2; ++nb) {
                        ffma2(acc2[mf][nh * 2 + nb][0], pa_r0[mf],
                              pack2(t[mf][nb][0], t[mf][nb][1]));
                        ffma2(acc2[mf][nh * 2 + nb][1], pa_r1[mf],
                              pack2(t[mf][nb][2], t[mf][nb][3]));
                    }
            }
        } else {
            const uint32_t* btu = reinterpret_cast<const uint32_t*>(bp);
            #pragma unroll
            for (int nh = 0; nh < 2; ++nh) {
                uint32_t bb[2];
                #pragma unroll
                for (int nb = 0; nb < 2; ++nb)
                    bb[nb] = btu[(wn * 4 + nh * 2 + nb) * 32 + lane];
                float t[2][2][4];
                #pragma unroll
                for (int mf = 0; mf < 2; ++mf)
                    #pragma unroll
                    for (int nb = 0; nb < 2; ++nb)
                        mma8z(t[mf][nb], hfT[mf][0], bb[nb]);
                #pragma unroll
                for (int mf = 0; mf < 2; ++mf)
                    #pragma unroll
                    for (int nb = 0; nb < 2; ++nb) {
                        ffma2(acc2[mf][nh * 2 + nb][0], pa_r0[mf],
                              pack2(t[mf][nb][0], t[mf][nb][1]));
                        ffma2(acc2[mf][nh * 2 + nb][1], pa_r1[mf],
                              pack2(t[mf][nb][2], t[mf][nb][3]));
                    }
            }
        }
    }

    // layer-2 epilogue
    __syncthreads();
    store_acc(H1s, acc2, mb, nbb, tq, tr);
    __syncthreads();
    write_out(out, H1s, b0, 128, tid);
}

// ---------------- launch ----------------
extern "C" void kernel_launch(void* const* d_in, const int* in_sizes, int n_in,
                              void* d_out, int out_size) {
    const float* x = nullptr;
    const float* W0 = nullptr;
    const float* W1 = nullptr;
    for (int i = 0; i < n_in; ++i) {
        if (in_sizes[i] == NB * F0V * DDIM)  x  = (const float*)d_in[i];
        else if (in_sizes[i] == 128 * P0)    W0 = (const float*)d_in[i];
        else if (in_sizes[i] == 128 * P1)    W1 = (const float*)d_in[i];
    }
    prep_kernel<<<512, 256>>>(W0, W1);
    cudaFuncSetAttribute(cin_kernel, cudaFuncAttributeMaxDynamicSharedMemorySize, SMEM_TOTAL);
    cin_kernel<<<512, NTHR, SMEM_TOTAL>>>(x, (float*)d_out);
}

// round 15
// speedup vs baseline: 1.7744x; 1.1917x over previous
#include <cuda_runtime.h>
#include <cuda_fp16.h>
#include <cstdint>

// ---------------- problem constants ----------------
#define NB     2048
#define F0V    39
#define DDIM   16
#define P0     1521
#define P1     4992

// chunk schedule (symmetrized layer-1):
//  pass 0: layer1, q-window [0,32), f=0..31 (W0 symmetrized: upper-tri doubled,
//          lower zero). Chunks f>=16 skip k-step 0 (q<16 < f impossible).
//  pass 1: layer1, q-window [32,40), f=0..38, Kc=8 (q=39 zero pad)
//  pass 2-5: layer2, q-window [32w,32w+32), f=0..38
#define NC0    32
#define NC1    39
#define NCL2   156              // 4*39
#define NCHUNK (NC0 + NC1 + NCL2)   // 227
#define L1END  (NC0 + NC1)      // 71

// W storage in packed f16x2 (uint32 units)
#define CSU_BIG 2048            // 128n x 32k halves / 2
#define CSU_SM  512             // 128n x 8k halves / 2
#define BASE_P1 (NC0 * CSU_BIG)             // 65536
#define BASE_P2 (BASE_P1 + NC1 * CSU_SM)    // 85504
#define WPU_TOTAL (BASE_P2 + NCL2 * CSU_BIG) // 404992

#define NTHR   128              // 4 CTAs / SM
#define NSTG   4                // cp.async stages
#define STGB   8192             // bytes per big stage
#define MROWS  32               // rows (2 batches x 16 d) per CTA

// ---------------- smem layout (bytes) ----------------
#define OFF_XT   0              // XsT: 40 x 32 fp32 (permuted) = 5120
#define OFF_H1   5120           // 32 x 132 fp32 = 16896
#define OFF_B    22016          // NSTG x 8192 W buffers
#define SMEM_TOTAL (OFF_B + NSTG * STGB)    // 54784 (x4 CTAs/SM = 219136)

__device__ __align__(16) uint32_t g_Wh[WPU_TOTAL];

// ---------------- helpers ----------------
__device__ __forceinline__ uint32_t smem_u32(const void* p) {
    uint32_t a;
    asm("{ .reg .u64 t; cvta.to.shared.u64 t, %1; cvt.u32.u64 %0, t; }" : "=r"(a) : "l"(p));
    return a;
}
// pack two fp32 -> f16x2 {lo=first arg, hi=second arg}. Used identically for A
// and B fragments, so any lo/hi convention is self-consistent in the MMA dot.
__device__ __forceinline__ uint32_t pk16(float lo, float hi) {
    uint32_t r;
    asm("cvt.rn.f16x2.f32 %0, %1, %2;" : "=r"(r) : "f"(hi), "f"(lo));
    return r;
}
// m16n8k16 fp16 MMA, fp32 accum, in place
__device__ __forceinline__ void mma16(float* c, const uint32_t* a, uint32_t b0, uint32_t b1) {
    asm volatile(
        "mma.sync.aligned.m16n8k16.row.col.f32.f16.f16.f32 "
        "{%0,%1,%2,%3},{%4,%5,%6,%7},{%8,%9},{%0,%1,%2,%3};"
        : "+f"(c[0]), "+f"(c[1]), "+f"(c[2]), "+f"(c[3])
        : "r"(a[0]), "r"(a[1]), "r"(a[2]), "r"(a[3]), "r"(b0), "r"(b1));
}
// zero-C form (no per-chunk accumulator init)
__device__ __forceinline__ void mma16z(float* d, const uint32_t* a, uint32_t b0, uint32_t b1) {
    asm volatile(
        "mma.sync.aligned.m16n8k16.row.col.f32.f16.f16.f32 "
        "{%0,%1,%2,%3},{%4,%5,%6,%7},{%8,%9},{%10,%10,%10,%10};"
        : "=f"(d[0]), "=f"(d[1]), "=f"(d[2]), "=f"(d[3])
        : "r"(a[0]), "r"(a[1]), "r"(a[2]), "r"(a[3]), "r"(b0), "r"(b1), "f"(0.0f));
}
// m16n8k8 fp16 MMA, zero-C (pass-1 Kc=8)
__device__ __forceinline__ void mma8z(float* d, const uint32_t* a, uint32_t b0) {
    asm volatile(
        "mma.sync.aligned.m16n8k8.row.col.f32.f16.f16.f32 "
        "{%0,%1,%2,%3},{%4,%5},{%6},{%7,%7,%7,%7};"
        : "=f"(d[0]), "=f"(d[1]), "=f"(d[2]), "=f"(d[3])
        : "r"(a[0]), "r"(a[1]), "r"(b0), "f"(0.0f));
}
// packed fp32x2
__device__ __forceinline__ uint64_t pack2(float lo, float hi) {
    uint64_t r; asm("mov.b64 %0, {%1,%2};" : "=l"(r) : "f"(lo), "f"(hi)); return r;
}
__device__ __forceinline__ uint64_t pack2s(float v) {
    uint64_t r; asm("mov.b64 %0, {%1,%1};" : "=l"(r) : "f"(v)); return r;
}
__device__ __forceinline__ void unpack2(uint64_t v, float& lo, float& hi) {
    asm("mov.b64 {%0,%1}, %2;" : "=f"(lo), "=f"(hi) : "l"(v));
}
__device__ __forceinline__ void ffma2(uint64_t& c, uint64_t a, uint64_t b) {
    asm("fma.rn.f32x2 %0, %1, %2, %0;" : "+l"(c) : "l"(a), "l"(b));
}

// symmetrized W0 value: q>f doubled pair sum, q==f diagonal, q<f (or pad) zero
__device__ __forceinline__ float symv(const float* __restrict__ W0, int n, int f, int q) {
    if (q > 38) return 0.0f;
    if (q > f)  return W0[n * P0 + f * F0V + q] + W0[n * P0 + q * F0V + f];
    if (q == f) return W0[n * P0 + f * F0V + q];
    return 0.0f;
}

// ---------------- prepass: W -> packed f16x2 fragment layout ----------------
// Big chunk (Kc=32): uint4[nbg(16)][lane(32)], components (lane: tq=lane/4, tr=lane%4):
//   comp c: k_even = (c>>1)*16 + (c&1)*8 + 2*tr ; pair (k_even, k_even+1); n = nbg*8+tq
// Small chunk (Kc=8): uint32[nbg(16)][lane(32)]: k_even = 2*tr; n = nbg*8+tq
__global__ void prep_kernel(const float* __restrict__ W0, const float* __restrict__ W1) {
    for (int idx = blockIdx.x * blockDim.x + threadIdx.x; idx < WPU_TOTAL;
         idx += gridDim.x * blockDim.x) {
        int p, f, u;
        if (idx < BASE_P1)      { p = 0; f = idx / CSU_BIG; u = idx % CSU_BIG; }
        else if (idx < BASE_P2) { int j = idx - BASE_P1; p = 1; f = j / CSU_SM; u = j % CSU_SM; }
        else {
            int j = idx - BASE_P2; int cc = j / CSU_BIG;
            p = 2 + cc / NC1; f = cc % NC1; u = j % CSU_BIG;
        }
        int n, ke;
        if (p == 1) {
            int lane = u & 31, nbg = u >> 5;
            n = nbg * 8 + (lane >> 2);
            ke = 2 * (lane & 3);
        } else {
            int comp = u & 3, lane = (u >> 2) & 31, nbg = u >> 7;
            n = nbg * 8 + (lane >> 2);
            ke = (comp >> 1) * 16 + (comp & 1) * 8 + 2 * (lane & 3);
        }
        float v0, v1;
        if (p == 0)      { v0 = symv(W0, n, f, ke);      v1 = symv(W0, n, f, ke + 1); }
        else if (p == 1) { v0 = symv(W0, n, f, 32 + ke); v1 = symv(W0, n, f, 33 + ke); }
        else {
            int q = 32 * (p - 2) + ke;
            v0 = W1[n * P1 + f * 128 + q];
            v1 = W1[n * P1 + f * 128 + q + 1];
        }
        g_Wh[idx] = pk16(v0, v1);
    }
}

// ---------------- chunk -> (p, f, base) ----------------
__device__ __forceinline__ void chunk_map(int c, int& p, int& f, uint32_t& base) {
    if (c < NC0)        { p = 0; f = c;        base = (uint32_t)c * CSU_BIG; }
    else if (c < L1END) { p = 1; f = c - NC0;  base = BASE_P1 + (uint32_t)(c - NC0) * CSU_SM; }
    else {
        int j = c - L1END;
        p = 2 + j / NC1; f = j % NC1;
        base = BASE_P2 + (uint32_t)j * CSU_BIG;
    }
}

// ---------------- cp.async W prefetch (128 threads) ----------------
__device__ __forceinline__ void prefetch_chunk(int c, uint32_t wsm, int tid) {
    int p, f; uint32_t base;
    chunk_map(c, p, f, base);
    const uint32_t* g = g_Wh + base;
    uint32_t dst = wsm + (c & (NSTG - 1)) * STGB;
    if (p != 1) {
        #pragma unroll
        for (int i = 0; i < 4; ++i)
            asm volatile("cp.async.cg.shared.global [%0], [%1], 16;"
                         :: "r"(dst + tid * 16 + i * 2048), "l"(g + tid * 4 + i * 512) : "memory");
    } else {
        asm volatile("cp.async.ca.shared.global [%0], [%1], 16;"
                     :: "r"(dst + tid * 16), "l"(g + tid * 4) : "memory");
    }
    asm volatile("cp.async.commit_group;" ::: "memory");
}

// ---------------- epilogue helpers ----------------
__device__ __forceinline__ void store_acc(float* H1s, const uint64_t acc2[2][4][2],
                                          int nbb, int tq, int tr) {
    #pragma unroll
    for (int mf = 0; mf < 2; ++mf)
        #pragma unroll
        for (int nb = 0; nb < 4; ++nb) {
            float a0, a1, a2, a3;
            unpack2(acc2[mf][nb][0], a0, a1);
            unpack2(acc2[mf][nb][1], a2, a3);
            int r0 = mf * 16 + tq;
            int col = nbb + nb * 8 + tr * 2;
            *reinterpret_cast<float2*>(&H1s[r0 * 132 + col]) = make_float2(a0, a1);
            *reinterpret_cast<float2*>(&H1s[(r0 + 8) * 132 + col]) = make_float2(a2, a3);
        }
}

__device__ __forceinline__ void write_out(float* __restrict__ out, const float* H1s,
                                          int b0, int colbase, int tid) {
    #pragma unroll
    for (int i = 0; i < 2; ++i) {
        int idx = tid + i * NTHR;         // 0..255
        int bl = idx >> 7, h = idx & 127;
        float s = 0.0f;
        #pragma unroll
        for (int d = 0; d < 16; ++d) s += H1s[(bl * 16 + d) * 132 + h];
        out[(size_t)(b0 + bl) * 256 + colbase + h] = s;
    }
}

// ---------------- main kernel ----------------
// 1024 CTAs (4/SM), M=32 rows per CTA, N=128. 4 warps, warp tile 32x32.
// Per chunk: t = H_f16 x W_f^T (fp16 HMMA, A pass-resident, zero-C first step),
//            acc += diag(x_f)*t via packed fma.rn.f32x2 (x exact fp32).
__global__ __launch_bounds__(NTHR, 4)
void cin_kernel(const float* __restrict__ x, float* __restrict__ out) {
    extern __shared__ char smem[];
    float* XsT = reinterpret_cast<float*>(smem + OFF_XT);   // permuted x^T [40][32]
    float* H1s = reinterpret_cast<float*>(smem + OFF_H1);   // [32][132]
    char*  wbuf = smem + OFF_B;
    const uint32_t wsm = smem_u32(wbuf);

    const int tid = threadIdx.x;
    const int lane = tid & 31, wn = tid >> 5;               // 4 warps = n-split
    const int tq = lane >> 2, tr = lane & 3;
    const int nbb = wn * 32;

    // ---- build XsT: XsT[(f*8+tq')*4 + j] = x[row=8j+tq', f]; f=39 zero pad ----
    const int b0 = blockIdx.x * 2;
    const float* xg = x + (size_t)b0 * (F0V * DDIM);
    for (int idx = tid; idx < 40 * MROWS; idx += NTHR) {
        int f = idx >> 5, row = idx & 31;
        float v = (f < F0V) ? xg[(row >> 4) * (F0V * DDIM) + f * DDIM + (row & 15)] : 0.0f;
        XsT[((f << 3) + (row & 7)) * 4 + (row >> 3)] = v;
    }
    __syncthreads();

    uint64_t acc2[2][4][2];
    #pragma unroll
    for (int a = 0; a < 2; ++a)
        #pragma unroll
        for (int b = 0; b < 4; ++b) { acc2[a][b][0] = 0ull; acc2[a][b][1] = 0ull; }

    uint32_t hfT[2][2][4];   // f16x2 A-fragments [mf][ks16][reg], pass-resident

    prefetch_chunk(0, wsm, tid);
    prefetch_chunk(1, wsm, tid);

    for (int c = 0; c < NCHUNK; ++c) {
        int p, f; uint32_t dummy;
        chunk_map(c, p, f, dummy);

        if ((c & 1) == 0) {
            // 1) separate prev-period readers from new writes
            __syncthreads();
            // 2) commit prefetches for c+2, c+3 FIRST, then wait past them for
            //    c, c+1 (committed last period -> full-period latency slack)
            if (c + 3 < NCHUNK) {
                prefetch_chunk(c + 2, wsm, tid);
                prefetch_chunk(c + 3, wsm, tid);
                asm volatile("cp.async.wait_group 2;" ::: "memory");
            } else if (c + 2 < NCHUNK) {
                prefetch_chunk(c + 2, wsm, tid);
                asm volatile("cp.async.wait_group 1;" ::: "memory");
            } else {
                asm volatile("cp.async.wait_group 0;" ::: "memory");
            }
            // 3) publish c, c+1 data to all threads
            __syncthreads();
        }

        if (c == L1END) {
            // layer-1 complete: D1 -> H1s, emit layer-1 output, reset acc
            store_acc(H1s, acc2, nbb, tq, tr);
            __syncthreads();
            write_out(out, H1s, b0, 0, tid);
            #pragma unroll
            for (int a = 0; a < 2; ++a)
                #pragma unroll
                for (int b = 0; b < 4; ++b) { acc2[a][b][0] = 0ull; acc2[a][b][1] = 0ull; }
        }

        if (f == 0) {
            // pass start: build fp16 A-fragments (once per pass)
            if (p < 2) {
                #pragma unroll
                for (int mf = 0; mf < 2; ++mf) {
                    if (p == 0) {
                        #pragma unroll
                        for (int ks = 0; ks < 2; ++ks) {
                            int q0 = ks * 16 + 2 * tr;
                            #pragma unroll
                            for (int half = 0; half < 2; ++half) {
                                int q = q0 + 8 * half;
                                int a0 = ((q << 3) + tq) * 4 + 2 * mf;
                                int a1 = (((q + 1) << 3) + tq) * 4 + 2 * mf;
                                hfT[mf][ks][2 * half + 0] = pk16(XsT[a0], XsT[a1]);
                                hfT[mf][ks][2 * half + 1] = pk16(XsT[a0 + 1], XsT[a1 + 1]);
                            }
                        }
                    } else {
                        int q = 32 + 2 * tr;
                        int a0 = ((q << 3) + tq) * 4 + 2 * mf;
                        int a1 = (((q + 1) << 3) + tq) * 4 + 2 * mf;
                        hfT[mf][0][0] = pk16(XsT[a0], XsT[a1]);
                        hfT[mf][0][1] = pk16(XsT[a0 + 1], XsT[a1 + 1]);
                    }
                }
            } else {
                const int qb = 32 * (p - 2);
                #pragma unroll
                for (int mf = 0; mf < 2; ++mf)
                    #pragma unroll
                    for (int ks = 0; ks < 2; ++ks) {
                        int r0 = mf * 16 + tq;
                        int q0 = qb + ks * 16 + 2 * tr;
                        hfT[mf][ks][0] = pk16(H1s[r0 * 132 + q0], H1s[r0 * 132 + q0 + 1]);
                        hfT[mf][ks][1] = pk16(H1s[(r0 + 8) * 132 + q0], H1s[(r0 + 8) * 132 + q0 + 1]);
                        hfT[mf][ks][2] = pk16(H1s[r0 * 132 + q0 + 8], H1s[r0 * 132 + q0 + 9]);
                        hfT[mf][ks][3] = pk16(H1s[(r0 + 8) * 132 + q0 + 8], H1s[(r0 + 8) * 132 + q0 + 9]);
                    }
            }
        }

        const char* bp = wbuf + (c & (NSTG - 1)) * STGB;

        // diagonal x0[row, f]: one broadcast LDS.128 per thread
        const float4 afv = *reinterpret_cast<const float4*>(XsT + ((f << 3) + tq) * 4);
        const uint64_t pa_r0[2] = { pack2s(afv.x), pack2s(afv.z) };   // rows tq (mf 0,1)
        const uint64_t pa_r1[2] = { pack2s(afv.y), pack2s(afv.w) };   // rows tq+8

        if (p != 1) {
            const bool only1 = (p == 0) && (f >= 16);   // symmetrized skip of k-step 0
            const uint4* bt = reinterpret_cast<const uint4*>(bp);
            #pragma unroll
            for (int nh = 0; nh < 2; ++nh) {
                uint4 bv[2];
                #pragma unroll
                for (int nb = 0; nb < 2; ++nb)
                    bv[nb] = bt[(wn * 4 + nh * 2 + nb) * 32 + lane];
                float t[2][2][4];
                #pragma unroll
                for (int mf = 0; mf < 2; ++mf)
                    #pragma unroll
                    for (int nb = 0; nb < 2; ++nb) {
                        if (only1) {
                            mma16z(t[mf][nb], hfT[mf][1], bv[nb].z, bv[nb].w);
                        } else {
                            mma16z(t[mf][nb], hfT[mf][0], bv[nb].x, bv[nb].y);
                            mma16(t[mf][nb], hfT[mf][1], bv[nb].z, bv[nb].w);
                        }
                    }
                #pragma unroll
                for (int mf = 0; mf < 2; ++mf)
                    #pragma unroll
                    for (int nb = 0; nb < 2; ++nb) {
                        ffma2(acc2[mf][nh * 2 + nb][0], pa_r0[mf],
                              pack2(t[mf][nb][0], t[mf][nb][1]));
                        ffma2(acc2[mf][nh * 2 + nb][1], pa_r1[mf],
                              pack2(t[mf][nb][2], t[mf][nb][3]));
                    }
            }
        } else {
            const uint32_t* btu = reinterpret_cast<const uint32_t*>(bp);
            #pragma unroll
            for (int nh = 0; nh < 2; ++nh) {
                uint32_t bb[2];
                #pragma unroll
                for (int nb = 0; nb < 2; ++nb)
                    bb[nb] = btu[(wn * 4 + nh * 2 + nb) * 32 + lane];
                float t[2][2][4];
                #pragma unroll
                for (int mf = 0; mf < 2; ++mf)
                    #pragma unroll
                    for (int nb = 0; nb < 2; ++nb)
                        mma8z(t[mf][nb], hfT[mf][0], bb[nb]);
                #pragma unroll
                for (int mf = 0; mf < 2; ++mf)
                    #pragma unroll
                    for (int nb = 0; nb < 2; ++nb) {
                        ffma2(acc2[mf][nh * 2 + nb][0], pa_r0[mf],
                              pack2(t[mf][nb][0], t[mf][nb][1]));
                        ffma2(acc2[mf][nh * 2 + nb][1], pa_r1[mf],
                              pack2(t[mf][nb][2], t[mf][nb][3]));
                    }
            }
        }
    }

    // layer-2 epilogue
    __syncthreads();
    store_acc(H1s, acc2, nbb, tq, tr);
    __syncthreads();
    write_out(out, H1s, b0, 128, tid);
}

// ---------------- launch ----------------
extern "C" void kernel_launch(void* const* d_in, const int* in_sizes, int n_in,
                              void* d_out, int out_size) {
    const float* x = nullptr;
    const float* W0 = nullptr;
    const float* W1 = nullptr;
    for (int i = 0; i < n_in; ++i) {
        if (in_sizes[i] == NB * F0V * DDIM)  x  = (const float*)d_in[i];
        else if (in_sizes[i] == 128 * P0)    W0 = (const float*)d_in[i];
        else if (in_sizes[i] == 128 * P1)    W1 = (const float*)d_in[i];
    }
    prep_kernel<<<512, 256>>>(W0, W1);
    cudaFuncSetAttribute(cin_kernel, cudaFuncAttributeMaxDynamicSharedMemorySize, SMEM_TOTAL);
    cin_kernel<<<1024, NTHR, SMEM_TOTAL>>>(x, (float*)d_out);
}

// round 17
// speedup vs baseline: 1.8485x; 1.0417x over previous
#include <cuda_runtime.h>
#include <cuda_fp16.h>
#include <cstdint>

// ---------------- problem constants ----------------
#define NB     2048
#define F0V    39
#define DDIM   16
#define P0     1521
#define P1     4992

// chunk schedule (symmetrized layer-1):
//  pass 0: layer1, q-window [0,32), f=0..31 (W0 symmetrized: upper-tri doubled,
//          lower zero). Chunks f>=16 skip k-step 0 (q<16 < f impossible).
//  pass 1: layer1, q-window [32,40), f=0..38, Kc=8 (q=39 zero pad)
//  pass 2-5: layer2, q-window [32w,32w+32), f=0..38
#define NC0    32
#define NC1    39
#define NCL2   156              // 4*39
#define NCHUNK (NC0 + NC1 + NCL2)   // 227
#define L1END  (NC0 + NC1)      // 71

// W storage in packed f16x2 (uint32 units); chunk-contiguous in schedule order
#define CSU_BIG 2048            // 128n x 32k halves / 2
#define CSU_SM  512             // 128n x 8k halves / 2
#define BASE_P1 (NC0 * CSU_BIG)             // 65536
#define BASE_P2 (BASE_P1 + NC1 * CSU_SM)    // 85504
#define WPU_TOTAL (BASE_P2 + NCL2 * CSU_BIG) // 404992

#define NTHR   128              // 4 CTAs / SM
#define NSTG   4                // cp.async stages
#define STGB   8192             // bytes per big stage
#define MROWS  32               // rows (2 batches x 16 d) per CTA

// ---------------- smem layout (bytes) ----------------
#define OFF_XT   0              // XsT: 40 x 32 fp32 (permuted) = 5120
#define OFF_H1   5120           // 32 x 132 fp32 = 16896
#define OFF_B    22016          // NSTG x 8192 W buffers
#define SMEM_TOTAL (OFF_B + NSTG * STGB)    // 54784 (x4 CTAs/SM = 219136)

__device__ __align__(16) uint32_t g_Wh[WPU_TOTAL];

// ---------------- helpers ----------------
__device__ __forceinline__ uint32_t smem_u32(const void* p) {
    uint32_t a;
    asm("{ .reg .u64 t; cvta.to.shared.u64 t, %1; cvt.u32.u64 %0, t; }" : "=r"(a) : "l"(p));
    return a;
}
// pack two fp32 -> f16x2 {lo=first arg, hi=second arg}. Used identically for A
// and B fragments, so any lo/hi convention is self-consistent in the MMA dot.
__device__ __forceinline__ uint32_t pk16(float lo, float hi) {
    uint32_t r;
    asm("cvt.rn.f16x2.f32 %0, %1, %2;" : "=r"(r) : "f"(hi), "f"(lo));
    return r;
}
// m16n8k16 fp16 MMA, fp32 accum, in place
__device__ __forceinline__ void mma16(float* c, const uint32_t* a, uint32_t b0, uint32_t b1) {
    asm volatile(
        "mma.sync.aligned.m16n8k16.row.col.f32.f16.f16.f32 "
        "{%0,%1,%2,%3},{%4,%5,%6,%7},{%8,%9},{%0,%1,%2,%3};"
        : "+f"(c[0]), "+f"(c[1]), "+f"(c[2]), "+f"(c[3])
        : "r"(a[0]), "r"(a[1]), "r"(a[2]), "r"(a[3]), "r"(b0), "r"(b1));
}
// zero-C form (no per-chunk accumulator init)
__device__ __forceinline__ void mma16z(float* d, const uint32_t* a, uint32_t b0, uint32_t b1) {
    asm volatile(
        "mma.sync.aligned.m16n8k16.row.col.f32.f16.f16.f32 "
        "{%0,%1,%2,%3},{%4,%5,%6,%7},{%8,%9},{%10,%10,%10,%10};"
        : "=f"(d[0]), "=f"(d[1]), "=f"(d[2]), "=f"(d[3])
        : "r"(a[0]), "r"(a[1]), "r"(a[2]), "r"(a[3]), "r"(b0), "r"(b1), "f"(0.0f));
}
// m16n8k8 fp16 MMA, zero-C (pass-1 Kc=8)
__device__ __forceinline__ void mma8z(float* d, const uint32_t* a, uint32_t b0) {
    asm volatile(
        "mma.sync.aligned.m16n8k8.row.col.f32.f16.f16.f32 "
        "{%0,%1,%2,%3},{%4,%5},{%6},{%7,%7,%7,%7};"
        : "=f"(d[0]), "=f"(d[1]), "=f"(d[2]), "=f"(d[3])
        : "r"(a[0]), "r"(a[1]), "r"(b0), "f"(0.0f));
}

// symmetrized W0 value: q>f doubled pair sum, q==f diagonal, q<f (or pad) zero
__device__ __forceinline__ float symv(const float* __restrict__ W0, int n, int f, int q) {
    if (q > 38) return 0.0f;
    if (q > f)  return W0[n * P0 + f * F0V + q] + W0[n * P0 + q * F0V + f];
    if (q == f) return W0[n * P0 + f * F0V + q];
    return 0.0f;
}

// ---------------- prepass: W -> packed f16x2 fragment layout ----------------
// Big chunk (Kc=32): uint4[nbg(16)][lane(32)], components (lane: tq=lane/4, tr=lane%4):
//   comp c: k_even = (c>>1)*16 + (c&1)*8 + 2*tr ; pair (k_even, k_even+1); n = nbg*8+tq
// Small chunk (Kc=8): uint32[nbg(16)][lane(32)]: k_even = 2*tr; n = nbg*8+tq
__global__ void prep_kernel(const float* __restrict__ W0, const float* __restrict__ W1) {
    for (int idx = blockIdx.x * blockDim.x + threadIdx.x; idx < WPU_TOTAL;
         idx += gridDim.x * blockDim.x) {
        int p, f, u;
        if (idx < BASE_P1)      { p = 0; f = idx / CSU_BIG; u = idx % CSU_BIG; }
        else if (idx < BASE_P2) { int j = idx - BASE_P1; p = 1; f = j / CSU_SM; u = j % CSU_SM; }
        else {
            int j = idx - BASE_P2; int cc = j / CSU_BIG;
            p = 2 + cc / NC1; f = cc % NC1; u = j % CSU_BIG;
        }
        int n, ke;
        if (p == 1) {
            int lane = u & 31, nbg = u >> 5;
            n = nbg * 8 + (lane >> 2);
            ke = 2 * (lane & 3);
        } else {
            int comp = u & 3, lane = (u >> 2) & 31, nbg = u >> 7;
            n = nbg * 8 + (lane >> 2);
            ke = (comp >> 1) * 16 + (comp & 1) * 8 + 2 * (lane & 3);
        }
        float v0, v1;
        if (p == 0)      { v0 = symv(W0, n, f, ke);      v1 = symv(W0, n, f, ke + 1); }
        else if (p == 1) { v0 = symv(W0, n, f, 32 + ke); v1 = symv(W0, n, f, 33 + ke); }
        else {
            int q = 32 * (p - 2) + ke;
            v0 = W1[n * P1 + f * 128 + q];
            v1 = W1[n * P1 + f * 128 + q + 1];
        }
        g_Wh[idx] = pk16(v0, v1);
    }
}

// ---------------- cp.async W prefetch (128 threads, division-free) ----------------
__device__ __forceinline__ void prefetch(uint32_t gbase, bool small, uint32_t dst, int tid) {
    const uint32_t* g = g_Wh + gbase;
    if (!small) {
        #pragma unroll
        for (int i = 0; i < 4; ++i)
            asm volatile("cp.async.cg.shared.global [%0], [%1], 16;"
                         :: "r"(dst + tid * 16 + i * 2048), "l"(g + tid * 4 + i * 512) : "memory");
    } else {
        asm volatile("cp.async.ca.shared.global [%0], [%1], 16;"
                     :: "r"(dst + tid * 16), "l"(g + tid * 4) : "memory");
    }
    asm volatile("cp.async.commit_group;" ::: "memory");
}

// ---------------- epilogue helpers ----------------
__device__ __forceinline__ void store_acc(float* H1s, const float acc[2][4][4],
                                          int nbb, int tq, int tr) {
    #pragma unroll
    for (int mf = 0; mf < 2; ++mf)
        #pragma unroll
        for (int nb = 0; nb < 4; ++nb) {
            int r0 = mf * 16 + tq;
            int col = nbb + nb * 8 + tr * 2;
            *reinterpret_cast<float2*>(&H1s[r0 * 132 + col]) =
                make_float2(acc[mf][nb][0], acc[mf][nb][1]);
            *reinterpret_cast<float2*>(&H1s[(r0 + 8) * 132 + col]) =
                make_float2(acc[mf][nb][2], acc[mf][nb][3]);
        }
}

__device__ __forceinline__ void write_out(float* __restrict__ out, const float* H1s,
                                          int b0, int colbase, int tid) {
    #pragma unroll
    for (int i = 0; i < 2; ++i) {
        int idx = tid + i * NTHR;         // 0..255
        int bl = idx >> 7, h = idx & 127;
        float s = 0.0f;
        #pragma unroll
        for (int d = 0; d < 16; ++d) s += H1s[(bl * 16 + d) * 132 + h];
        out[(size_t)(b0 + bl) * 256 + colbase + h] = s;
    }
}

// ---------------- main kernel ----------------
// 1024 CTAs (4/SM), M=32 rows per CTA, N=128. 4 warps, warp tile 32x32.
// Per chunk: t = H_f16 x W_f^T (fp16 HMMA, A pass-resident, zero-C first step),
//            acc += diag(x_f)*t via scalar FFMA (x exact fp32).
// All chunk bookkeeping is division-free incremental state.
__global__ __launch_bounds__(NTHR, 4)
void cin_kernel(const float* __restrict__ x, float* __restrict__ out) {
    extern __shared__ char smem[];
    float* XsT = reinterpret_cast<float*>(smem + OFF_XT);   // permuted x^T [40][32]
    float* H1s = reinterpret_cast<float*>(smem + OFF_H1);   // [32][132]
    char*  wbuf = smem + OFF_B;
    const uint32_t wsm = smem_u32(wbuf);

    const int tid = threadIdx.x;
    const int lane = tid & 31, wn = tid >> 5;               // 4 warps = n-split
    const int tq = lane >> 2, tr = lane & 3;
    const int nbb = wn * 32;

    // ---- build XsT: XsT[(f*8+tq')*4 + j] = x[row=8j+tq', f]; f=39 zero pad ----
    const int b0 = blockIdx.x * 2;
    const float* xg = x + (size_t)b0 * (F0V * DDIM);
    for (int idx = tid; idx < 40 * MROWS; idx += NTHR) {
        int f = idx >> 5, row = idx & 31;
        float v = (f < F0V) ? xg[(row >> 4) * (F0V * DDIM) + f * DDIM + (row & 15)] : 0.0f;
        XsT[((f << 3) + (row & 7)) * 4 + (row >> 3)] = v;
    }
    __syncthreads();

    float acc[2][4][4];
    #pragma unroll
    for (int a = 0; a < 2; ++a)
        #pragma unroll
        for (int b = 0; b < 4; ++b)
            #pragma unroll
            for (int e = 0; e < 4; ++e) acc[a][b][e] = 0.0f;

    uint32_t hfT[2][2][4];   // f16x2 A-fragments [mf][ks16][reg], pass-resident

    // initial prefetch: chunks 0, 1
    prefetch(0, false, wsm + 0 * STGB, tid);
    prefetch(CSU_BIG, false, wsm + 1 * STGB, tid);

    // prefetch cursor -> chunk 2
    uint32_t pc_base = 2 * CSU_BIG;
    int pc_rem = NC0 - 2;        // chunks left in cursor's pass
    int pc_p = 0;
    bool pc_small = false;

    // body state -> chunk 0
    int p = 0, f = 0;

    for (int c = 0; c < NCHUNK; ++c) {
        if ((c & 1) == 0) {
            // 1) separate prev-period readers from new writes
            __syncthreads();
            // 2) commit prefetches for c+2, c+3 first, then wait past them
            if (c + 3 < NCHUNK) {
                #pragma unroll
                for (int k = 0; k < 2; ++k) {
                    prefetch(pc_base, pc_small, wsm + ((c + 2 + k) & 3) * STGB, tid);
                    pc_base += pc_small ? CSU_SM : CSU_BIG;
                    if (--pc_rem == 0) { ++pc_p; pc_rem = NC1; pc_small = (pc_p == 1); }
                }
                asm volatile("cp.async.wait_group 2;" ::: "memory");
            } else if (c + 2 < NCHUNK) {
                prefetch(pc_base, pc_small, wsm + ((c + 2) & 3) * STGB, tid);
                pc_base += pc_small ? CSU_SM : CSU_BIG;
                if (--pc_rem == 0) { ++pc_p; pc_rem = NC1; pc_small = (pc_p == 1); }
                asm volatile("cp.async.wait_group 1;" ::: "memory");
            } else {
                asm volatile("cp.async.wait_group 0;" ::: "memory");
            }
            // 3) publish c, c+1 data to all threads
            __syncthreads();
        }

        if (c == L1END) {
            // layer-1 complete: D1 -> H1s, emit layer-1 output, reset acc
            store_acc(H1s, acc, nbb, tq, tr);
            __syncthreads();
            write_out(out, H1s, b0, 0, tid);
            #pragma unroll
            for (int a = 0; a < 2; ++a)
                #pragma unroll
                for (int b = 0; b < 4; ++b)
                    #pragma unroll
                    for (int e = 0; e < 4; ++e) acc[a][b][e] = 0.0f;
        }

        if (f == 0) {
            // pass start: build fp16 A-fragments (once per pass)
            if (p < 2) {
                #pragma unroll
                for (int mf = 0; mf < 2; ++mf) {
                    if (p == 0) {
                        #pragma unroll
                        for (int ks = 0; ks < 2; ++ks) {
                            int q0 = ks * 16 + 2 * tr;
                            #pragma unroll
                            for (int half = 0; half < 2; ++half) {
                                int q = q0 + 8 * half;
                                int a0 = ((q << 3) + tq) * 4 + 2 * mf;
                                int a1 = (((q + 1) << 3) + tq) * 4 + 2 * mf;
                                hfT[mf][ks][2 * half + 0] = pk16(XsT[a0], XsT[a1]);
                                hfT[mf][ks][2 * half + 1] = pk16(XsT[a0 + 1], XsT[a1 + 1]);
                            }
                        }
                    } else {
                        int q = 32 + 2 * tr;
                        int a0 = ((q << 3) + tq) * 4 + 2 * mf;
                        int a1 = (((q + 1) << 3) + tq) * 4 + 2 * mf;
                        hfT[mf][0][0] = pk16(XsT[a0], XsT[a1]);
                        hfT[mf][0][1] = pk16(XsT[a0 + 1], XsT[a1 + 1]);
                    }
                }
            } else {
                const int qb = 32 * (p - 2);
                #pragma unroll
                for (int mf = 0; mf < 2; ++mf)
                    #pragma unroll
                    for (int ks = 0; ks < 2; ++ks) {
                        int r0 = mf * 16 + tq;
                        int q0 = qb + ks * 16 + 2 * tr;
                        hfT[mf][ks][0] = pk16(H1s[r0 * 132 + q0], H1s[r0 * 132 + q0 + 1]);
                        hfT[mf][ks][1] = pk16(H1s[(r0 + 8) * 132 + q0], H1s[(r0 + 8) * 132 + q0 + 1]);
                        hfT[mf][ks][2] = pk16(H1s[r0 * 132 + q0 + 8], H1s[r0 * 132 + q0 + 9]);
                        hfT[mf][ks][3] = pk16(H1s[(r0 + 8) * 132 + q0 + 8], H1s[(r0 + 8) * 132 + q0 + 9]);
                    }
            }
        }

        const char* bp = wbuf + (c & (NSTG - 1)) * STGB;

        // diagonal x0[row, f]: one broadcast LDS.128 per thread
        // afv.{x,y,z,w} = x0 at rows {tq, tq+8, tq+16, tq+24}
        const float4 afv = *reinterpret_cast<const float4*>(XsT + ((f << 3) + tq) * 4);

        if (p != 1) {
            const bool only1 = (p == 0) && (f >= 16);   // symmetrized skip of k-step 0
            const uint4* bt = reinterpret_cast<const uint4*>(bp);
            #pragma unroll
            for (int nh = 0; nh < 2; ++nh) {
                uint4 bv[2];
                #pragma unroll
                for (int nb = 0; nb < 2; ++nb)
                    bv[nb] = bt[(wn * 4 + nh * 2 + nb) * 32 + lane];
                float t[2][2][4];
                #pragma unroll
                for (int mf = 0; mf < 2; ++mf)
                    #pragma unroll
                    for (int nb = 0; nb < 2; ++nb) {
                        if (only1) {
                            mma16z(t[mf][nb], hfT[mf][1], bv[nb].z, bv[nb].w);
                        } else {
                            mma16z(t[mf][nb], hfT[mf][0], bv[nb].x, bv[nb].y);
                            mma16(t[mf][nb], hfT[mf][1], bv[nb].z, bv[nb].w);
                        }
                    }
                #pragma unroll
                for (int mf = 0; mf < 2; ++mf)
                    #pragma unroll
                    for (int nb = 0; nb < 2; ++nb) {
                        float* A = acc[mf][nh * 2 + nb];
                        const float af0 = mf ? afv.z : afv.x;
                        const float af1 = mf ? afv.w : afv.y;
                        A[0] += af0 * t[mf][nb][0];
                        A[1] += af0 * t[mf][nb][1];
                        A[2] += af1 * t[mf][nb][2];
                        A[3] += af1 * t[mf][nb][3];
                    }
            }
        } else {
            const uint32_t* btu = reinterpret_cast<const uint32_t*>(bp);
            #pragma unroll
            for (int nh = 0; nh < 2; ++nh) {
                uint32_t bb[2];
                #pragma unroll
                for (int nb = 0; nb < 2; ++nb)
                    bb[nb] = btu[(wn * 4 + nh * 2 + nb) * 32 + lane];
                float t[2][2][4];
                #pragma unroll
                for (int mf = 0; mf < 2; ++mf)
                    #pragma unroll
                    for (int nb = 0; nb < 2; ++nb)
                        mma8z(t[mf][nb], hfT[mf][0], bb[nb]);
                #pragma unroll
                for (int mf = 0; mf < 2; ++mf)
                    #pragma unroll
                    for (int nb = 0; nb < 2; ++nb) {
                        float* A = acc[mf][nh * 2 + nb];
                        const float af0 = mf ? afv.z : afv.x;
                        const float af1 = mf ? afv.w : afv.y;
                        A[0] += af0 * t[mf][nb][0];
                        A[1] += af0 * t[mf][nb][1];
                        A[2] += af1 * t[mf][nb][2];
                        A[3] += af1 * t[mf][nb][3];
                    }
            }
        }

        // advance body state (division-free)
        if (++f == ((p == 0) ? NC0 : NC1)) { f = 0; ++p; }
    }

    // layer-2 epilogue
    __syncthreads();
    store_acc(H1s, acc, nbb, tq, tr);
    __syncthreads();
    write_out(out, H1s, b0, 128, tid);
}

// ---------------- launch ----------------
extern "C" void kernel_launch(void* const* d_in, const int* in_sizes, int n_in,
                              void* d_out, int out_size) {
    const float* x = nullptr;
    const float* W0 = nullptr;
    const float* W1 = nullptr;
    for (int i = 0; i < n_in; ++i) {
        if (in_sizes[i] == NB * F0V * DDIM)  x  = (const float*)d_in[i];
        else if (in_sizes[i] == 128 * P0)    W0 = (const float*)d_in[i];
        else if (in_sizes[i] == 128 * P1)    W1 = (const float*)d_in[i];
    }
    prep_kernel<<<512, 256>>>(W0, W1);
    cudaFuncSetAttribute(cin_kernel, cudaFuncAttributeMaxDynamicSharedMemorySize, SMEM_TOTAL);
    cin_kernel<<<1024, NTHR, SMEM_TOTAL>>>(x, (float*)d_out);
}